// round 1
// baseline (speedup 1.0000x reference)
#include <cuda_runtime.h>
#include <cuda_bf16.h>
#include <math.h>

// Problem constants
#define Bn   128
#define HW   49
#define Cc   2048
#define Dh   2048
#define De   128
#define Nrow (Bn*HW)          // 6272
#define INV_TAU 5.0f

// ---------------- scratch (device globals; no runtime allocation) ------------
__device__ float g_poolq[Bn*Cc];
__device__ float g_poolk[Bn*Cc];
__device__ float g_hid[(size_t)Nrow*Dh];          // 51.4 MB, reused 4x
__device__ float g_qg[Bn*De];
__device__ float g_kg[Bn*De];
__device__ float g_qd[(size_t)Nrow*De];
__device__ float g_kd[(size_t)Nrow*De];
__device__ float g_matched[(size_t)Nrow*De];
__device__ float g_S[(size_t)Nrow*Nrow];          // 157 MB logits (pre-1/tau)
__device__ float g_pos[Nrow];
__device__ float g_lg[Bn];
__device__ float g_ld[Nrow];

// ---------------- pooling: mean over 49 pixels -------------------------------
__global__ void pool_kernel(const float* __restrict__ f, float* __restrict__ g) {
    int b = blockIdx.y;
    int c = blockIdx.x * 256 + threadIdx.x;
    const float* p = f + (size_t)b * HW * Cc + c;
    float s = 0.f;
#pragma unroll
    for (int i = 0; i < HW; i++) s += p[(size_t)i * Cc];
    g[(size_t)b * Cc + c] = s * (1.0f / 49.0f);
}

// ---------------- SGEMM: C[M,N] = A[M,K] @ B  (+bias, opt relu) --------------
// TRANSB=false: B is [K,N] row-major.  TRANSB=true: B is [N,K] row-major.
#define BM 128
#define BN 128
#define BK 16
#define TM 8
#define TN 8

template <bool RELU, bool TRANSB>
__global__ __launch_bounds__(256, 2)
void sgemm_kernel(const float* __restrict__ A, const float* __restrict__ B,
                  const float* __restrict__ bias, float* __restrict__ C,
                  int M, int N, int K) {
    __shared__ float As[BK][BM];
    __shared__ float Bs[BK][BN];

    const int bm = blockIdx.y * BM;
    const int bn = blockIdx.x * BN;
    const int tid = threadIdx.x;
    const int tx = tid & 15;          // 0..15  -> N direction
    const int ty = tid >> 4;          // 0..15  -> M direction

    float acc[TM][TN];
#pragma unroll
    for (int i = 0; i < TM; i++)
#pragma unroll
        for (int j = 0; j < TN; j++) acc[i][j] = 0.f;

    for (int k0 = 0; k0 < K; k0 += BK) {
        // load A tile (128 x 16), store transposed As[k][m]
#pragma unroll
        for (int t = tid; t < BM * BK / 4; t += 256) {
            int row = t >> 2, c4 = t & 3;
            float4 v = *(const float4*)(A + (size_t)(bm + row) * K + k0 + c4 * 4);
            As[c4 * 4 + 0][row] = v.x;
            As[c4 * 4 + 1][row] = v.y;
            As[c4 * 4 + 2][row] = v.z;
            As[c4 * 4 + 3][row] = v.w;
        }
        if (!TRANSB) {
            // B tile (16 x 128) straight copy
#pragma unroll
            for (int t = tid; t < BK * BN / 4; t += 256) {
                int row = t >> 5, c4 = t & 31;
                float4 v = *(const float4*)(B + (size_t)(k0 + row) * N + bn + c4 * 4);
                *(float4*)&Bs[row][c4 * 4] = v;
            }
        } else {
            // B is [N,K]; need Bs[k][n] = B[bn+n][k0+k]
#pragma unroll
            for (int t = tid; t < BN * BK / 4; t += 256) {
                int row = t >> 2, c4 = t & 3;
                float4 v = *(const float4*)(B + (size_t)(bn + row) * K + k0 + c4 * 4);
                Bs[c4 * 4 + 0][row] = v.x;
                Bs[c4 * 4 + 1][row] = v.y;
                Bs[c4 * 4 + 2][row] = v.z;
                Bs[c4 * 4 + 3][row] = v.w;
            }
        }
        __syncthreads();

#pragma unroll
        for (int k = 0; k < BK; k++) {
            float a[TM], b[TN];
#pragma unroll
            for (int i = 0; i < TM; i++) a[i] = As[k][ty * TM + i];
#pragma unroll
            for (int j = 0; j < TN; j++) b[j] = Bs[k][tx * TN + j];
#pragma unroll
            for (int i = 0; i < TM; i++)
#pragma unroll
                for (int j = 0; j < TN; j++)
                    acc[i][j] = fmaf(a[i], b[j], acc[i][j]);
        }
        __syncthreads();
    }

#pragma unroll
    for (int i = 0; i < TM; i++) {
        int m = bm + ty * TM + i;
#pragma unroll
        for (int j = 0; j < TN; j++) {
            int n = bn + tx * TN + j;
            float v = acc[i][j];
            if (bias) v += bias[n];
            if (RELU) v = fmaxf(v, 0.f);
            C[(size_t)m * N + n] = v;
        }
    }
}

// ---------------- row-wise l2 normalize (rows of 128) ------------------------
__global__ void l2norm_kernel(float* __restrict__ x, int rows) {
    int row = blockIdx.x * 8 + threadIdx.y;
    if (row >= rows) return;
    float* p = x + (size_t)row * De;
    int lane = threadIdx.x;
    float4 v = *(float4*)(p + lane * 4);
    float ss = v.x * v.x + v.y * v.y + v.z * v.z + v.w * v.w;
#pragma unroll
    for (int o = 16; o; o >>= 1) ss += __shfl_xor_sync(0xFFFFFFFFu, ss, o);
    float r = 1.0f / sqrtf(fmaxf(ss, 1e-12f));
    v.x *= r; v.y *= r; v.z *= r; v.w *= r;
    *(float4*)(p + lane * 4) = v;
}

// ---------------- global InfoNCE (128x128) -----------------------------------
__global__ void lg_kernel(const float* __restrict__ qg,
                          const float* __restrict__ kg,
                          float* __restrict__ out) {
    int row = blockIdx.x;
    __shared__ float qs[De];
    __shared__ float red[128];
    int t = threadIdx.x;   // 128 threads
    qs[t] = qg[(size_t)row * De + t];
    __syncthreads();
    const float* kp = kg + (size_t)t * De;
    float dot = 0.f;
#pragma unroll 8
    for (int c = 0; c < De; c++) dot = fmaf(qs[c], kp[c], dot);
    float logit = dot * INV_TAU;

    red[t] = logit; __syncthreads();
    for (int s = 64; s; s >>= 1) { if (t < s) red[t] = fmaxf(red[t], red[t + s]); __syncthreads(); }
    float m = red[0]; __syncthreads();
    red[t] = expf(logit - m); __syncthreads();
    for (int s = 64; s; s >>= 1) { if (t < s) red[t] += red[t + s]; __syncthreads(); }
    float lse = m + logf(red[0]);
    if (t == row) out[row] = lse - logit;
}

// ---------------- per-batch argmax matching ----------------------------------
__global__ void match_kernel(const float* __restrict__ qd,
                             const float* __restrict__ kd,
                             float* __restrict__ matched,
                             float* __restrict__ pos) {
    int row = blockIdx.x;             // 0..6271
    int b = row / HW;
    __shared__ float qs[De];
    __shared__ float dots[64];
    __shared__ int   s_idx;
    __shared__ float s_val;
    int t = threadIdx.x;              // 128 threads
    qs[t] = qd[(size_t)row * De + t];
    __syncthreads();
    if (t < HW) {
        const float* kp = kd + (size_t)(b * HW + t) * De;
        float d = 0.f;
#pragma unroll 8
        for (int c = 0; c < De; c++) d = fmaf(qs[c], kp[c], d);
        dots[t] = d;
    }
    __syncthreads();
    if (t == 0) {
        float bv = dots[0]; int bi = 0;
        for (int j = 1; j < HW; j++)
            if (dots[j] > bv) { bv = dots[j]; bi = j; }   // strict > == first-occurrence argmax
        s_idx = bi; s_val = bv;
    }
    __syncthreads();
    matched[(size_t)row * De + t] = kd[(size_t)(b * HW + s_idx) * De + t];
    if (t == 0) pos[row] = s_val;
}

// ---------------- row logsumexp over S (raw dots; scale by 1/tau here) -------
__global__ void row_lse_kernel(const float* __restrict__ S,
                               const float* __restrict__ pos,
                               float* __restrict__ out, int N) {
    int row = blockIdx.x;
    const float* p = S + (size_t)row * N;
    int t = threadIdx.x;              // 256 threads, each sees >= 24 elements
    float m = -3.402823466e38f, s = 0.f;
    for (int j = t; j < N; j += 256) {
        float x = p[j] * INV_TAU;
        if (x > m) { s = s * expf(m - x) + 1.f; m = x; }
        else       { s += expf(x - m); }
    }
    __shared__ float ms[256], ssh[256];
    ms[t] = m; ssh[t] = s; __syncthreads();
    for (int o = 128; o; o >>= 1) {
        if (t < o) {
            float m2 = ms[t + o], s2 = ssh[t + o];
            float mm = fmaxf(ms[t], m2);
            ssh[t] = ssh[t] * expf(ms[t] - mm) + s2 * expf(m2 - mm);
            ms[t] = mm;
        }
        __syncthreads();
    }
    if (t == 0) out[row] = ms[0] + logf(ssh[0]) - pos[row] * INV_TAU;
}

// ---------------- final reduction -------------------------------------------
__global__ void final_kernel(const float* __restrict__ lg,
                             const float* __restrict__ ld,
                             float* __restrict__ out) {
    int t = threadIdx.x;              // 256 threads
    float s1 = 0.f, s2 = 0.f;
    if (t < Bn) s1 = lg[t];
    for (int j = t; j < Nrow; j += 256) s2 += ld[j];
    __shared__ float r1[256], r2[256];
    r1[t] = s1; r2[t] = s2; __syncthreads();
    for (int o = 128; o; o >>= 1) {
        if (t < o) { r1[t] += r1[t + o]; r2[t] += r2[t + o]; }
        __syncthreads();
    }
    if (t == 0) out[0] = 0.5f * (r1[0] / (float)Bn) + 0.5f * (r2[0] / (float)Nrow);
}

// ---------------- host orchestration -----------------------------------------
extern "C" void kernel_launch(void* const* d_in, const int* in_sizes, int n_in,
                              void* d_out, int out_size) {
    const float* feat_q = (const float*)d_in[0];
    const float* feat_k = (const float*)d_in[1];
    const float* Wg1  = (const float*)d_in[2];
    const float* bg1  = (const float*)d_in[3];
    const float* Wg2  = (const float*)d_in[4];
    const float* bg2  = (const float*)d_in[5];
    const float* Wd1  = (const float*)d_in[6];
    const float* bd1  = (const float*)d_in[7];
    const float* Wd2  = (const float*)d_in[8];
    const float* bd2  = (const float*)d_in[9];
    const float* mWg1 = (const float*)d_in[10];
    const float* mbg1 = (const float*)d_in[11];
    const float* mWg2 = (const float*)d_in[12];
    const float* mbg2 = (const float*)d_in[13];
    const float* mWd1 = (const float*)d_in[14];
    const float* mbd1 = (const float*)d_in[15];
    const float* mWd2 = (const float*)d_in[16];
    const float* mbd2 = (const float*)d_in[17];
    float* out = (float*)d_out;

    float *poolq, *poolk, *hid, *qg, *kg, *qd, *kd, *matched, *S, *pos, *lg, *ld;
    cudaGetSymbolAddress((void**)&poolq,   g_poolq);
    cudaGetSymbolAddress((void**)&poolk,   g_poolk);
    cudaGetSymbolAddress((void**)&hid,     g_hid);
    cudaGetSymbolAddress((void**)&qg,      g_qg);
    cudaGetSymbolAddress((void**)&kg,      g_kg);
    cudaGetSymbolAddress((void**)&qd,      g_qd);
    cudaGetSymbolAddress((void**)&kd,      g_kd);
    cudaGetSymbolAddress((void**)&matched, g_matched);
    cudaGetSymbolAddress((void**)&S,       g_S);
    cudaGetSymbolAddress((void**)&pos,     g_pos);
    cudaGetSymbolAddress((void**)&lg,      g_lg);
    cudaGetSymbolAddress((void**)&ld,      g_ld);

    dim3 poolGrid(Cc / 256, Bn);

    // ---- global head ----
    pool_kernel<<<poolGrid, 256>>>(feat_q, poolq);
    pool_kernel<<<poolGrid, 256>>>(feat_k, poolk);

    sgemm_kernel<true,  false><<<dim3(Dh / BN, Bn / BM), 256>>>(poolq, Wg1, bg1, hid, Bn, Dh, Cc);
    sgemm_kernel<false, false><<<dim3(De / BN, Bn / BM), 256>>>(hid, Wg2, bg2, qg, Bn, De, Dh);
    l2norm_kernel<<<(Bn + 7) / 8, dim3(32, 8)>>>(qg, Bn);

    sgemm_kernel<true,  false><<<dim3(Dh / BN, Bn / BM), 256>>>(poolk, mWg1, mbg1, hid, Bn, Dh, Cc);
    sgemm_kernel<false, false><<<dim3(De / BN, Bn / BM), 256>>>(hid, mWg2, mbg2, kg, Bn, De, Dh);
    l2norm_kernel<<<(Bn + 7) / 8, dim3(32, 8)>>>(kg, Bn);

    lg_kernel<<<Bn, 128>>>(qg, kg, lg);

    // ---- dense head (query) ----
    sgemm_kernel<true,  false><<<dim3(Dh / BN, Nrow / BM), 256>>>(feat_q, Wd1, bd1, hid, Nrow, Dh, Cc);
    sgemm_kernel<false, false><<<dim3(De / BN, Nrow / BM), 256>>>(hid, Wd2, bd2, qd, Nrow, De, Dh);
    l2norm_kernel<<<Nrow / 8, dim3(32, 8)>>>(qd, Nrow);

    // ---- dense head (key / momentum) ----
    sgemm_kernel<true,  false><<<dim3(Dh / BN, Nrow / BM), 256>>>(feat_k, mWd1, mbd1, hid, Nrow, Dh, Cc);
    sgemm_kernel<false, false><<<dim3(De / BN, Nrow / BM), 256>>>(hid, mWd2, mbd2, kd, Nrow, De, Dh);
    l2norm_kernel<<<Nrow / 8, dim3(32, 8)>>>(kd, Nrow);

    // ---- matching + dense InfoNCE ----
    match_kernel<<<Nrow, 128>>>(qd, kd, matched, pos);
    sgemm_kernel<false, true><<<dim3(Nrow / BN, Nrow / BM), 256>>>(qd, matched, nullptr, S, Nrow, Nrow, De);
    row_lse_kernel<<<Nrow, 256>>>(S, pos, ld, Nrow);

    final_kernel<<<1, 256>>>(lg, ld, out);
}

// round 3
// speedup vs baseline: 2.8548x; 2.8548x over previous
#include <cuda_runtime.h>
#include <cuda_bf16.h>
#include <math.h>
#include <stdint.h>

#define Bn   128
#define HW   49
#define Cc   2048
#define Dh   2048
#define De   128
#define Nrow (Bn*HW)          // 6272
#define INV_TAU 5.0f

typedef __nv_bfloat16 bf16;

// ========================= PTX helpers (compute_103-safe) ====================
__device__ __forceinline__ uint32_t smem_u32(const void* p) {
    uint32_t a;
    asm("{ .reg .u64 t; cvta.to.shared.u64 t, %1; cvt.u32.u64 %0, t; }" : "=r"(a) : "l"(p));
    return a;
}
__device__ __forceinline__ void cp16(uint32_t dst, const void* src) {
    asm volatile("cp.async.cg.shared.global [%0], [%1], 16;" :: "r"(dst), "l"(src));
}
#define CP_COMMIT() asm volatile("cp.async.commit_group;" ::: "memory")
#define CP_WAIT0()  asm volatile("cp.async.wait_group 0;" ::: "memory")
#define LDS32(v, a) asm volatile("ld.shared.b32 %0, [%1];" : "=r"(v) : "r"(a))

__device__ __forceinline__ void mma16816(float* c, const uint32_t* a, const uint32_t* b) {
    asm volatile("mma.sync.aligned.m16n8k16.row.col.f32.bf16.bf16.f32 "
        "{%0,%1,%2,%3}, {%4,%5,%6,%7}, {%8,%9}, {%0,%1,%2,%3};"
        : "+f"(c[0]), "+f"(c[1]), "+f"(c[2]), "+f"(c[3])
        : "r"(a[0]), "r"(a[1]), "r"(a[2]), "r"(a[3]), "r"(b[0]), "r"(b[1]));
}

// ========================= scratch buffers ===================================
__device__ __align__(256) bf16 g_WgT1h[Dh*Cc],  g_WgT1l[Dh*Cc];
__device__ __align__(256) bf16 g_WdT1h[Dh*Cc],  g_WdT1l[Dh*Cc];
__device__ __align__(256) bf16 g_mWgT1h[Dh*Cc], g_mWgT1l[Dh*Cc];
__device__ __align__(256) bf16 g_mWdT1h[Dh*Cc], g_mWdT1l[Dh*Cc];
__device__ __align__(256) bf16 g_WgT2h[De*Dh],  g_WgT2l[De*Dh];
__device__ __align__(256) bf16 g_WdT2h[De*Dh],  g_WdT2l[De*Dh];
__device__ __align__(256) bf16 g_mWgT2h[De*Dh], g_mWgT2l[De*Dh];
__device__ __align__(256) bf16 g_mWdT2h[De*Dh], g_mWdT2l[De*Dh];
__device__ __align__(256) bf16 g_Aqh[(size_t)Nrow*Cc], g_Aql[(size_t)Nrow*Cc];
__device__ __align__(256) bf16 g_Akh[(size_t)Nrow*Cc], g_Akl[(size_t)Nrow*Cc];
__device__ __align__(256) bf16 g_pqh[Bn*Cc], g_pql[Bn*Cc], g_pkh[Bn*Cc], g_pkl[Bn*Cc];
__device__ __align__(256) bf16 g_ghh[Bn*Dh], g_ghl[Bn*Dh];
__device__ __align__(256) bf16 g_hidh[(size_t)Nrow*Dh], g_hidl[(size_t)Nrow*Dh];
__device__ __align__(256) bf16 g_qdh[Nrow*De], g_qdl[Nrow*De];
__device__ __align__(256) bf16 g_mth[Nrow*De], g_mtl[Nrow*De];
__device__ __align__(256) float g_part[4*(size_t)Nrow*De];
__device__ float g_qg[Bn*De], g_kg[Bn*De];
__device__ float g_qd[Nrow*De], g_kd[Nrow*De];
__device__ float g_S[(size_t)Nrow*Nrow];
__device__ float g_pos[Nrow], g_lg[Bn], g_ld[Nrow];

// ========================= pre-pass kernels ==================================
__global__ void transpose_split(const float* __restrict__ W, bf16* __restrict__ Th,
                                bf16* __restrict__ Tl, int K, int N) {
    __shared__ float t[32][33];
    int n0 = blockIdx.x * 32, k0 = blockIdx.y * 32;
    int tx = threadIdx.x, ty = threadIdx.y;
#pragma unroll
    for (int j = 0; j < 32; j += 8)
        t[ty + j][tx] = W[(size_t)(k0 + ty + j) * N + n0 + tx];
    __syncthreads();
#pragma unroll
    for (int j = 0; j < 32; j += 8) {
        float v = t[tx][ty + j];
        bf16 h = __float2bfloat16(v);
        size_t o = (size_t)(n0 + ty + j) * K + k0 + tx;
        Th[o] = h;
        Tl[o] = __float2bfloat16(v - __bfloat162float(h));
    }
}

__global__ void convert_split(const float* __restrict__ x, bf16* __restrict__ h,
                              bf16* __restrict__ l, size_t n4) {
    size_t i = (size_t)blockIdx.x * 256 + threadIdx.x;
    if (i >= n4) return;
    float4 v = ((const float4*)x)[i];
    bf16 h0 = __float2bfloat16(v.x), h1 = __float2bfloat16(v.y);
    bf16 h2 = __float2bfloat16(v.z), h3 = __float2bfloat16(v.w);
    __nv_bfloat162 ph0; ph0.x = h0; ph0.y = h1;
    __nv_bfloat162 ph1; ph1.x = h2; ph1.y = h3;
    ((__nv_bfloat162*)h)[i*2]   = ph0;
    ((__nv_bfloat162*)h)[i*2+1] = ph1;
    __nv_bfloat162 pl0, pl1;
    pl0.x = __float2bfloat16(v.x - __bfloat162float(h0));
    pl0.y = __float2bfloat16(v.y - __bfloat162float(h1));
    pl1.x = __float2bfloat16(v.z - __bfloat162float(h2));
    pl1.y = __float2bfloat16(v.w - __bfloat162float(h3));
    ((__nv_bfloat162*)l)[i*2]   = pl0;
    ((__nv_bfloat162*)l)[i*2+1] = pl1;
}

__global__ void pool_split(const float* __restrict__ f, bf16* __restrict__ h,
                           bf16* __restrict__ l) {
    int b = blockIdx.y;
    int c = blockIdx.x * 256 + threadIdx.x;
    const float* p = f + (size_t)b * HW * Cc + c;
    float s = 0.f;
#pragma unroll
    for (int i = 0; i < HW; i++) s += p[(size_t)i * Cc];
    s *= (1.0f / 49.0f);
    bf16 hi = __float2bfloat16(s);
    h[(size_t)b * Cc + c] = hi;
    l[(size_t)b * Cc + c] = __float2bfloat16(s - __bfloat162float(hi));
}

// ========================= mma.sync GEMM =====================================
// D[m][n] = sum_k A[m][k]*B[n][k], split-bf16 (Ah*Bh + Ah*Bl + Al*Bh), fp32 accum.
// Tile 128x128, BK=32, cp.async double buffer.
// EPI 0: fp32 out (+bias if non-null), EPI 1: bias+relu -> bf16 hi/lo out.
#define ROWB 80                 // 32 bf16 (64B) + 16B pad per smem row
#define MATB (128*ROWB)         // 10240
#define STGB (4*MATB)           // 40960 per stage
#define SM_TOTAL (2*STGB)       // 81920

template<int EPI>
__global__ __launch_bounds__(256)
void gemm_mma(const bf16* __restrict__ Ah, const bf16* __restrict__ Al,
              const bf16* __restrict__ Bh, const bf16* __restrict__ Bl,
              const float* __restrict__ bias,
              float* __restrict__ Cf, bf16* __restrict__ Chi, bf16* __restrict__ Clo,
              int M, int N, int ldA, int ldB, int klen) {
    extern __shared__ char smem[];
    const uint32_t sb = smem_u32(smem);
    const int tid = threadIdx.x;
    const int wid = tid >> 5;
    const int lid = tid & 31;
    const int wm = wid >> 2;          // 0..1  (64 rows each)
    const int wn = wid & 3;           // 0..3  (32 cols each)
    const int g = lid >> 2;           // 0..7
    const int t = lid & 3;            // 0..3
    const int bm = blockIdx.y * 128;
    const int bn = blockIdx.x * 128;
    const int kbeg = blockIdx.z * klen;
    const int nch = klen / 32;

    const bf16* baseA_h = Ah + (size_t)bm * ldA + kbeg;
    const bf16* baseA_l = Al + (size_t)bm * ldA + kbeg;
    const bf16* baseB_h = Bh + (size_t)bn * ldB + kbeg;
    const bf16* baseB_l = Bl + (size_t)bn * ldB + kbeg;

    // per-thread load slots: 2 per matrix (512 rows-of-16B per matrix / 256 thr)
    const int r0 = tid >> 2, c0 = tid & 3;                 // slot 0
    const int r1 = (tid + 256) >> 2, c1 = tid & 3;         // slot 1

    float acc[4][4][4];
#pragma unroll
    for (int i = 0; i < 4; i++)
#pragma unroll
        for (int j = 0; j < 4; j++)
#pragma unroll
            for (int c = 0; c < 4; c++) acc[i][j][c] = 0.f;

    // ---- prologue: load chunk 0 into stage 0 ----
    {
        const int k0 = 0;
        uint32_t st = sb;
        cp16(st + 0*MATB + r0*ROWB + c0*16, baseA_h + (size_t)r0*ldA + k0 + c0*8);
        cp16(st + 0*MATB + r1*ROWB + c1*16, baseA_h + (size_t)r1*ldA + k0 + c1*8);
        cp16(st + 1*MATB + r0*ROWB + c0*16, baseA_l + (size_t)r0*ldA + k0 + c0*8);
        cp16(st + 1*MATB + r1*ROWB + c1*16, baseA_l + (size_t)r1*ldA + k0 + c1*8);
        cp16(st + 2*MATB + r0*ROWB + c0*16, baseB_h + (size_t)r0*ldB + k0 + c0*8);
        cp16(st + 2*MATB + r1*ROWB + c1*16, baseB_h + (size_t)r1*ldB + k0 + c1*8);
        cp16(st + 3*MATB + r0*ROWB + c0*16, baseB_l + (size_t)r0*ldB + k0 + c0*8);
        cp16(st + 3*MATB + r1*ROWB + c1*16, baseB_l + (size_t)r1*ldB + k0 + c1*8);
        CP_COMMIT();
    }

    const uint32_t aoff = (uint32_t)((wm*64 + g)*ROWB + t*4);
    const uint32_t boff = (uint32_t)((wn*32 + g)*ROWB + t*4);

    for (int ch = 0; ch < nch; ch++) {
        CP_WAIT0();
        __syncthreads();
        if (ch + 1 < nch) {
            const int k0 = (ch + 1) * 32;
            uint32_t st = sb + ((ch + 1) & 1) * STGB;
            cp16(st + 0*MATB + r0*ROWB + c0*16, baseA_h + (size_t)r0*ldA + k0 + c0*8);
            cp16(st + 0*MATB + r1*ROWB + c1*16, baseA_h + (size_t)r1*ldA + k0 + c1*8);
            cp16(st + 1*MATB + r0*ROWB + c0*16, baseA_l + (size_t)r0*ldA + k0 + c0*8);
            cp16(st + 1*MATB + r1*ROWB + c1*16, baseA_l + (size_t)r1*ldA + k0 + c1*8);
            cp16(st + 2*MATB + r0*ROWB + c0*16, baseB_h + (size_t)r0*ldB + k0 + c0*8);
            cp16(st + 2*MATB + r1*ROWB + c1*16, baseB_h + (size_t)r1*ldB + k0 + c1*8);
            cp16(st + 3*MATB + r0*ROWB + c0*16, baseB_l + (size_t)r0*ldB + k0 + c0*8);
            cp16(st + 3*MATB + r1*ROWB + c1*16, baseB_l + (size_t)r1*ldB + k0 + c1*8);
            CP_COMMIT();
        }
        const uint32_t st = sb + (ch & 1) * STGB;
#pragma unroll
        for (int ks = 0; ks < 2; ks++) {
            uint32_t ah[4][4], al[4][4], bh[4][2], bl[4][2];
#pragma unroll
            for (int i = 0; i < 4; i++) {
                uint32_t a = st + aoff + i*(16*ROWB) + ks*32;
                LDS32(ah[i][0], a);        LDS32(ah[i][1], a + 8*ROWB);
                LDS32(ah[i][2], a + 16);   LDS32(ah[i][3], a + 8*ROWB + 16);
                uint32_t a2 = a + MATB;
                LDS32(al[i][0], a2);       LDS32(al[i][1], a2 + 8*ROWB);
                LDS32(al[i][2], a2 + 16);  LDS32(al[i][3], a2 + 8*ROWB + 16);
            }
#pragma unroll
            for (int j = 0; j < 4; j++) {
                uint32_t b = st + 2*MATB + boff + j*(8*ROWB) + ks*32;
                LDS32(bh[j][0], b);        LDS32(bh[j][1], b + 16);
                LDS32(bl[j][0], b + MATB); LDS32(bl[j][1], b + MATB + 16);
            }
#pragma unroll
            for (int i = 0; i < 4; i++)
#pragma unroll
                for (int j = 0; j < 4; j++) {
                    mma16816(acc[i][j], ah[i], bh[j]);
                    mma16816(acc[i][j], ah[i], bl[j]);
                    mma16816(acc[i][j], al[i], bh[j]);
                }
        }
        __syncthreads();
    }

    // ---- epilogue: direct global stores ----
    const size_t zoff = (size_t)blockIdx.z * M * N;
#pragma unroll
    for (int i = 0; i < 4; i++) {
        int row0 = bm + wm*64 + i*16 + g;
#pragma unroll
        for (int j = 0; j < 4; j++) {
            int col = bn + wn*32 + j*8 + 2*t;
            float b0 = 0.f, b1 = 0.f;
            if (bias) { b0 = bias[col]; b1 = bias[col + 1]; }
#pragma unroll
            for (int h = 0; h < 2; h++) {
                int row = row0 + h*8;
                float v0 = acc[i][j][2*h]     + b0;
                float v1 = acc[i][j][2*h + 1] + b1;
                size_t o = (size_t)row * N + col;
                if (EPI == 1) {
                    v0 = fmaxf(v0, 0.f); v1 = fmaxf(v1, 0.f);
                    bf16 h0 = __float2bfloat16(v0), h1 = __float2bfloat16(v1);
                    __nv_bfloat162 ph; ph.x = h0; ph.y = h1;
                    *(__nv_bfloat162*)&Chi[o] = ph;
                    __nv_bfloat162 pl;
                    pl.x = __float2bfloat16(v0 - __bfloat162float(h0));
                    pl.y = __float2bfloat16(v1 - __bfloat162float(h1));
                    *(__nv_bfloat162*)&Clo[o] = pl;
                } else {
                    float2 fv; fv.x = v0; fv.y = v1;
                    *(float2*)&Cf[zoff + o] = fv;
                }
            }
        }
    }
}

// split-K reduction.  EPI 0: fp32 out (+bias).  EPI 1: bias+relu -> bf16 hi/lo
template<int EPI>
__global__ void reduce_split(const float* __restrict__ part, const float* __restrict__ bias,
                             float* __restrict__ Cf, bf16* __restrict__ Chi, bf16* __restrict__ Clo,
                             int S, size_t MN, int N) {
    size_t i4 = (size_t)blockIdx.x * 256 + threadIdx.x;
    if (i4 * 4 >= MN) return;
    float4 a = {0.f, 0.f, 0.f, 0.f};
    for (int s = 0; s < S; s++) {
        float4 v = *(const float4*)(part + s * MN + i4 * 4);
        a.x += v.x; a.y += v.y; a.z += v.z; a.w += v.w;
    }
    size_t base = i4 * 4;
    int n = (int)(base % N);
    a.x += bias[n]; a.y += bias[n+1]; a.z += bias[n+2]; a.w += bias[n+3];
    if (EPI == 1) {
        a.x = fmaxf(a.x, 0.f); a.y = fmaxf(a.y, 0.f);
        a.z = fmaxf(a.z, 0.f); a.w = fmaxf(a.w, 0.f);
        bf16 h0 = __float2bfloat16(a.x), h1 = __float2bfloat16(a.y);
        bf16 h2 = __float2bfloat16(a.z), h3 = __float2bfloat16(a.w);
        __nv_bfloat162 p0; p0.x = h0; p0.y = h1;
        __nv_bfloat162 p1; p1.x = h2; p1.y = h3;
        *(__nv_bfloat162*)&Chi[base]     = p0;
        *(__nv_bfloat162*)&Chi[base + 2] = p1;
        __nv_bfloat162 q0, q1;
        q0.x = __float2bfloat16(a.x - __bfloat162float(h0));
        q0.y = __float2bfloat16(a.y - __bfloat162float(h1));
        q1.x = __float2bfloat16(a.z - __bfloat162float(h2));
        q1.y = __float2bfloat16(a.w - __bfloat162float(h3));
        *(__nv_bfloat162*)&Clo[base]     = q0;
        *(__nv_bfloat162*)&Clo[base + 2] = q1;
    } else {
        *(float4*)&Cf[base] = a;
    }
}

// ========================= small kernels (fp32 path) =========================
__global__ void l2norm_kernel(float* __restrict__ x, int rows) {
    int row = blockIdx.x * 8 + threadIdx.y;
    if (row >= rows) return;
    float* p = x + (size_t)row * De;
    int lane = threadIdx.x;
    float4 v = *(float4*)(p + lane * 4);
    float ss = v.x*v.x + v.y*v.y + v.z*v.z + v.w*v.w;
#pragma unroll
    for (int o = 16; o; o >>= 1) ss += __shfl_xor_sync(0xFFFFFFFFu, ss, o);
    float r = 1.0f / sqrtf(fmaxf(ss, 1e-12f));
    v.x *= r; v.y *= r; v.z *= r; v.w *= r;
    *(float4*)(p + lane * 4) = v;
}

__global__ void l2norm_split(float* __restrict__ x, bf16* __restrict__ h,
                             bf16* __restrict__ l, int rows) {
    int row = blockIdx.x * 8 + threadIdx.y;
    if (row >= rows) return;
    float* p = x + (size_t)row * De;
    int lane = threadIdx.x;
    float4 v = *(float4*)(p + lane * 4);
    float ss = v.x*v.x + v.y*v.y + v.z*v.z + v.w*v.w;
#pragma unroll
    for (int o = 16; o; o >>= 1) ss += __shfl_xor_sync(0xFFFFFFFFu, ss, o);
    float r = 1.0f / sqrtf(fmaxf(ss, 1e-12f));
    v.x *= r; v.y *= r; v.z *= r; v.w *= r;
    *(float4*)(p + lane * 4) = v;
    size_t o = (size_t)row * De + lane * 4;
    bf16 h0 = __float2bfloat16(v.x), h1 = __float2bfloat16(v.y);
    bf16 h2 = __float2bfloat16(v.z), h3 = __float2bfloat16(v.w);
    __nv_bfloat162 p0; p0.x = h0; p0.y = h1;
    __nv_bfloat162 p1; p1.x = h2; p1.y = h3;
    *(__nv_bfloat162*)&h[o]     = p0;
    *(__nv_bfloat162*)&h[o + 2] = p1;
    __nv_bfloat162 q0, q1;
    q0.x = __float2bfloat16(v.x - __bfloat162float(h0));
    q0.y = __float2bfloat16(v.y - __bfloat162float(h1));
    q1.x = __float2bfloat16(v.z - __bfloat162float(h2));
    q1.y = __float2bfloat16(v.w - __bfloat162float(h3));
    *(__nv_bfloat162*)&l[o]     = q0;
    *(__nv_bfloat162*)&l[o + 2] = q1;
}

__global__ void lg_kernel(const float* __restrict__ qg, const float* __restrict__ kg,
                          float* __restrict__ out) {
    int row = blockIdx.x;
    __shared__ float qs[De];
    __shared__ float red[128];
    int t = threadIdx.x;
    qs[t] = qg[(size_t)row * De + t];
    __syncthreads();
    const float* kp = kg + (size_t)t * De;
    float dot = 0.f;
#pragma unroll 8
    for (int c = 0; c < De; c++) dot = fmaf(qs[c], kp[c], dot);
    float logit = dot * INV_TAU;
    red[t] = logit; __syncthreads();
    for (int s = 64; s; s >>= 1) { if (t < s) red[t] = fmaxf(red[t], red[t + s]); __syncthreads(); }
    float m = red[0]; __syncthreads();
    red[t] = expf(logit - m); __syncthreads();
    for (int s = 64; s; s >>= 1) { if (t < s) red[t] += red[t + s]; __syncthreads(); }
    float lse = m + logf(red[0]);
    if (t == row) out[row] = lse - logit;
}

__global__ void match_kernel(const float* __restrict__ qd, const float* __restrict__ kd,
                             bf16* __restrict__ mh, bf16* __restrict__ ml,
                             float* __restrict__ pos) {
    int row = blockIdx.x;
    int b = row / HW;
    __shared__ float qs[De];
    __shared__ float dots[64];
    __shared__ int   s_idx;
    __shared__ float s_val;
    int t = threadIdx.x;
    qs[t] = qd[(size_t)row * De + t];
    __syncthreads();
    if (t < HW) {
        const float* kp = kd + (size_t)(b * HW + t) * De;
        float d = 0.f;
#pragma unroll 8
        for (int c = 0; c < De; c++) d = fmaf(qs[c], kp[c], d);
        dots[t] = d;
    }
    __syncthreads();
    if (t == 0) {
        float bv = dots[0]; int bi = 0;
        for (int j = 1; j < HW; j++)
            if (dots[j] > bv) { bv = dots[j]; bi = j; }
        s_idx = bi; s_val = bv;
    }
    __syncthreads();
    float v = kd[(size_t)(b * HW + s_idx) * De + t];
    bf16 h = __float2bfloat16(v);
    mh[(size_t)row * De + t] = h;
    ml[(size_t)row * De + t] = __float2bfloat16(v - __bfloat162float(h));
    if (t == 0) pos[row] = s_val;
}

__global__ void row_lse_kernel(const float* __restrict__ S, const float* __restrict__ pos,
                               float* __restrict__ out, int N) {
    int row = blockIdx.x;
    const float* p = S + (size_t)row * N;
    int t = threadIdx.x;
    float m = -3.402823466e38f, s = 0.f;
    for (int j = t; j < N; j += 256) {
        float x = p[j] * INV_TAU;
        if (x > m) { s = s * expf(m - x) + 1.f; m = x; }
        else       { s += expf(x - m); }
    }
    __shared__ float ms[256], ssh[256];
    ms[t] = m; ssh[t] = s; __syncthreads();
    for (int o = 128; o; o >>= 1) {
        if (t < o) {
            float m2 = ms[t + o], s2 = ssh[t + o];
            float mm = fmaxf(ms[t], m2);
            ssh[t] = ssh[t] * expf(ms[t] - mm) + s2 * expf(m2 - mm);
            ms[t] = mm;
        }
        __syncthreads();
    }
    if (t == 0) out[row] = ms[0] + logf(ssh[0]) - pos[row] * INV_TAU;
}

__global__ void final_kernel(const float* __restrict__ lg, const float* __restrict__ ld,
                             float* __restrict__ out) {
    int t = threadIdx.x;
    float s1 = 0.f, s2 = 0.f;
    if (t < Bn) s1 = lg[t];
    for (int j = t; j < Nrow; j += 256) s2 += ld[j];
    __shared__ float r1[256], r2[256];
    r1[t] = s1; r2[t] = s2; __syncthreads();
    for (int o = 128; o; o >>= 1) {
        if (t < o) { r1[t] += r1[t + o]; r2[t] += r2[t + o]; }
        __syncthreads();
    }
    if (t == 0) out[0] = 0.5f * (r1[0] / (float)Bn) + 0.5f * (r2[0] / (float)Nrow);
}

// ========================= host orchestration ================================
extern "C" void kernel_launch(void* const* d_in, const int* in_sizes, int n_in,
                              void* d_out, int out_size) {
    const float* feat_q = (const float*)d_in[0];
    const float* feat_k = (const float*)d_in[1];
    const float* Wg1  = (const float*)d_in[2];   const float* bg1 = (const float*)d_in[3];
    const float* Wg2  = (const float*)d_in[4];   const float* bg2 = (const float*)d_in[5];
    const float* Wd1  = (const float*)d_in[6];   const float* bd1 = (const float*)d_in[7];
    const float* Wd2  = (const float*)d_in[8];   const float* bd2 = (const float*)d_in[9];
    const float* mWg1 = (const float*)d_in[10];  const float* mbg1 = (const float*)d_in[11];
    const float* mWg2 = (const float*)d_in[12];  const float* mbg2 = (const float*)d_in[13];
    const float* mWd1 = (const float*)d_in[14];  const float* mbd1 = (const float*)d_in[15];
    const float* mWd2 = (const float*)d_in[16];  const float* mbd2 = (const float*)d_in[17];
    float* out = (float*)d_out;

    cudaFuncSetAttribute(gemm_mma<0>, cudaFuncAttributeMaxDynamicSharedMemorySize, SM_TOTAL);
    cudaFuncSetAttribute(gemm_mma<1>, cudaFuncAttributeMaxDynamicSharedMemorySize, SM_TOTAL);

#define SYM(p, s) cudaGetSymbolAddress((void**)&p, s)
    bf16 *WgT1h, *WgT1l, *WdT1h, *WdT1l, *mWgT1h, *mWgT1l, *mWdT1h, *mWdT1l;
    bf16 *WgT2h, *WgT2l, *WdT2h, *WdT2l, *mWgT2h, *mWgT2l, *mWdT2h, *mWdT2l;
    bf16 *Aqh, *Aql, *Akh, *Akl, *pqh, *pql, *pkh, *pkl, *ghh, *ghl, *hidh, *hidl;
    bf16 *qdh, *qdl, *mth, *mtl;
    float *part, *qg, *kg, *qd, *kd, *S, *pos, *lg, *ld;
    SYM(WgT1h, g_WgT1h); SYM(WgT1l, g_WgT1l); SYM(WdT1h, g_WdT1h); SYM(WdT1l, g_WdT1l);
    SYM(mWgT1h, g_mWgT1h); SYM(mWgT1l, g_mWgT1l); SYM(mWdT1h, g_mWdT1h); SYM(mWdT1l, g_mWdT1l);
    SYM(WgT2h, g_WgT2h); SYM(WgT2l, g_WgT2l); SYM(WdT2h, g_WdT2h); SYM(WdT2l, g_WdT2l);
    SYM(mWgT2h, g_mWgT2h); SYM(mWgT2l, g_mWgT2l); SYM(mWdT2h, g_mWdT2h); SYM(mWdT2l, g_mWdT2l);
    SYM(Aqh, g_Aqh); SYM(Aql, g_Aql); SYM(Akh, g_Akh); SYM(Akl, g_Akl);
    SYM(pqh, g_pqh); SYM(pql, g_pql); SYM(pkh, g_pkh); SYM(pkl, g_pkl);
    SYM(ghh, g_ghh); SYM(ghl, g_ghl); SYM(hidh, g_hidh); SYM(hidl, g_hidl);
    SYM(qdh, g_qdh); SYM(qdl, g_qdl); SYM(mth, g_mth); SYM(mtl, g_mtl);
    SYM(part, g_part); SYM(qg, g_qg); SYM(kg, g_kg); SYM(qd, g_qd); SYM(kd, g_kd);
    SYM(S, g_S); SYM(pos, g_pos); SYM(lg, g_lg); SYM(ld, g_ld);
#undef SYM

    // ---- pre-pass: weight transposes + activation splits ----
    dim3 tb(32, 8);
    transpose_split<<<dim3(Dh/32, Cc/32), tb>>>(Wg1,  WgT1h,  WgT1l,  Cc, Dh);
    transpose_split<<<dim3(Dh/32, Cc/32), tb>>>(Wd1,  WdT1h,  WdT1l,  Cc, Dh);
    transpose_split<<<dim3(Dh/32, Cc/32), tb>>>(mWg1, mWgT1h, mWgT1l, Cc, Dh);
    transpose_split<<<dim3(Dh/32, Cc/32), tb>>>(mWd1, mWdT1h, mWdT1l, Cc, Dh);
    transpose_split<<<dim3(De/32, Dh/32), tb>>>(Wg2,  WgT2h,  WgT2l,  Dh, De);
    transpose_split<<<dim3(De/32, Dh/32), tb>>>(Wd2,  WdT2h,  WdT2l,  Dh, De);
    transpose_split<<<dim3(De/32, Dh/32), tb>>>(mWg2, mWgT2h, mWgT2l, Dh, De);
    transpose_split<<<dim3(De/32, Dh/32), tb>>>(mWd2, mWdT2h, mWdT2l, Dh, De);

    size_t featN4 = (size_t)Nrow * Cc / 4;
    convert_split<<<(unsigned)((featN4 + 255) / 256), 256>>>(feat_q, Aqh, Aql, featN4);
    convert_split<<<(unsigned)((featN4 + 255) / 256), 256>>>(feat_k, Akh, Akl, featN4);
    pool_split<<<dim3(Cc/256, Bn), 256>>>(feat_q, pqh, pql);
    pool_split<<<dim3(Cc/256, Bn), 256>>>(feat_k, pkh, pkl);

    // ---- global head (q) ----
    gemm_mma<0><<<dim3(Dh/128, 1, 8), 256, SM_TOTAL>>>(pqh, pql, WgT1h, WgT1l, nullptr,
        part, nullptr, nullptr, Bn, Dh, Cc, Cc, Cc/8);
    reduce_split<1><<<(Bn*Dh/4 + 255)/256, 256>>>(part, bg1, nullptr, ghh, ghl, 8, (size_t)Bn*Dh, Dh);
    gemm_mma<0><<<dim3(1, 1, 16), 256, SM_TOTAL>>>(ghh, ghl, WgT2h, WgT2l, nullptr,
        part, nullptr, nullptr, Bn, De, Dh, Dh, Dh/16);
    reduce_split<0><<<(Bn*De/4 + 255)/256, 256>>>(part, bg2, qg, nullptr, nullptr, 16, (size_t)Bn*De, De);
    // ---- global head (k) ----
    gemm_mma<0><<<dim3(Dh/128, 1, 8), 256, SM_TOTAL>>>(pkh, pkl, mWgT1h, mWgT1l, nullptr,
        part, nullptr, nullptr, Bn, Dh, Cc, Cc, Cc/8);
    reduce_split<1><<<(Bn*Dh/4 + 255)/256, 256>>>(part, mbg1, nullptr, ghh, ghl, 8, (size_t)Bn*Dh, Dh);
    gemm_mma<0><<<dim3(1, 1, 16), 256, SM_TOTAL>>>(ghh, ghl, mWgT2h, mWgT2l, nullptr,
        part, nullptr, nullptr, Bn, De, Dh, Dh, Dh/16);
    reduce_split<0><<<(Bn*De/4 + 255)/256, 256>>>(part, mbg2, kg, nullptr, nullptr, 16, (size_t)Bn*De, De);

    l2norm_kernel<<<(Bn + 7)/8, dim3(32, 8)>>>(qg, Bn);
    l2norm_kernel<<<(Bn + 7)/8, dim3(32, 8)>>>(kg, Bn);
    lg_kernel<<<Bn, 128>>>(qg, kg, lg);

    // ---- dense head (q) ----
    gemm_mma<1><<<dim3(Dh/128, Nrow/128, 1), 256, SM_TOTAL>>>(Aqh, Aql, WdT1h, WdT1l, bd1,
        nullptr, hidh, hidl, Nrow, Dh, Cc, Cc, Cc);
    gemm_mma<0><<<dim3(1, Nrow/128, 4), 256, SM_TOTAL>>>(hidh, hidl, WdT2h, WdT2l, nullptr,
        part, nullptr, nullptr, Nrow, De, Dh, Dh, Dh/4);
    reduce_split<0><<<(Nrow*De/4 + 255)/256, 256>>>(part, bd2, qd, nullptr, nullptr, 4, (size_t)Nrow*De, De);
    // ---- dense head (k) ----
    gemm_mma<1><<<dim3(Dh/128, Nrow/128, 1), 256, SM_TOTAL>>>(Akh, Akl, mWdT1h, mWdT1l, mbd1,
        nullptr, hidh, hidl, Nrow, Dh, Cc, Cc, Cc);
    gemm_mma<0><<<dim3(1, Nrow/128, 4), 256, SM_TOTAL>>>(hidh, hidl, mWdT2h, mWdT2l, nullptr,
        part, nullptr, nullptr, Nrow, De, Dh, Dh, Dh/4);
    reduce_split<0><<<(Nrow*De/4 + 255)/256, 256>>>(part, mbd2, kd, nullptr, nullptr, 4, (size_t)Nrow*De, De);

    l2norm_split<<<Nrow/8, dim3(32, 8)>>>(qd, qdh, qdl, Nrow);
    l2norm_kernel<<<Nrow/8, dim3(32, 8)>>>(kd, Nrow);

    // ---- matching + dense InfoNCE ----
    match_kernel<<<Nrow, 128>>>(qd, kd, mth, mtl, pos);
    gemm_mma<0><<<dim3(Nrow/128, Nrow/128, 1), 256, SM_TOTAL>>>(qdh, qdl, mth, mtl, nullptr,
        S, nullptr, nullptr, Nrow, Nrow, De, De, De);
    row_lse_kernel<<<Nrow, 256>>>(S, pos, ld, Nrow);

    final_kernel<<<1, 256>>>(lg, ld, out);
}

// round 4
// speedup vs baseline: 3.6303x; 1.2717x over previous
#include <cuda_runtime.h>
#include <cuda_bf16.h>
#include <math.h>
#include <stdint.h>

#define Bn   128
#define HW   49
#define Cc   2048
#define Dh   2048
#define De   128
#define Nrow (Bn*HW)          // 6272
#define INV_TAU 5.0f

typedef __nv_bfloat16 bf16;

// ========================= PTX helpers (compute_103-safe) ====================
__device__ __forceinline__ uint32_t smem_u32(const void* p) {
    uint32_t a;
    asm("{ .reg .u64 t; cvta.to.shared.u64 t, %1; cvt.u32.u64 %0, t; }" : "=r"(a) : "l"(p));
    return a;
}
__device__ __forceinline__ void cp16(uint32_t dst, const void* src) {
    asm volatile("cp.async.cg.shared.global [%0], [%1], 16;" :: "r"(dst), "l"(src));
}
#define CP_COMMIT() asm volatile("cp.async.commit_group;" ::: "memory")
#define CP_WAIT0()  asm volatile("cp.async.wait_group 0;" ::: "memory")
#define LDMX4(r0, r1, r2, r3, addr)                                            \
    asm volatile("ldmatrix.sync.aligned.m8n8.x4.shared.b16 {%0,%1,%2,%3}, [%4];" \
        : "=r"(r0), "=r"(r1), "=r"(r2), "=r"(r3) : "r"(addr))

__device__ __forceinline__ void mma16816(float* c, const uint32_t* a, const uint32_t* b) {
    asm volatile("mma.sync.aligned.m16n8k16.row.col.f32.bf16.bf16.f32 "
        "{%0,%1,%2,%3}, {%4,%5,%6,%7}, {%8,%9}, {%0,%1,%2,%3};"
        : "+f"(c[0]), "+f"(c[1]), "+f"(c[2]), "+f"(c[3])
        : "r"(a[0]), "r"(a[1]), "r"(a[2]), "r"(a[3]), "r"(b[0]), "r"(b[1]));
}

// ========================= scratch buffers ===================================
// Interleaved hi|lo layout: row stride 2K, lo at +K within the row.
__device__ __align__(256) bf16 g_Wd1T[(size_t)Dh*2*Cc];
__device__ __align__(256) bf16 g_mWd1T[(size_t)Dh*2*Cc];
__device__ __align__(256) bf16 g_Wg1T[(size_t)Dh*2*Cc];
__device__ __align__(256) bf16 g_mWg1T[(size_t)Dh*2*Cc];
__device__ __align__(256) bf16 g_Wg2T[De*2*Dh], g_Wd2T[De*2*Dh];
__device__ __align__(256) bf16 g_mWg2T[De*2*Dh], g_mWd2T[De*2*Dh];
__device__ __align__(256) bf16 g_Aq[(size_t)Nrow*2*Cc], g_Ak[(size_t)Nrow*2*Cc];
__device__ __align__(256) bf16 g_pq[Bn*2*Cc], g_pk[Bn*2*Cc];
__device__ __align__(256) bf16 g_gh[2*(size_t)Bn*2*Dh];
__device__ __align__(256) bf16 g_hid[2*(size_t)Nrow*2*Dh];
__device__ __align__(256) bf16 g_qdm[Nrow*2*De], g_mt[Nrow*2*De];
__device__ __align__(256) float g_part[8*(size_t)Nrow*De];
__device__ float g_qg[Bn*De], g_kg[Bn*De];
__device__ float g_qd[Nrow*De], g_kd[Nrow*De];
__device__ float g_S[(size_t)Nrow*Nrow];
__device__ float g_pos[Nrow], g_lg[Bn], g_ld[Nrow];

// ========================= pre-pass kernels ==================================
// transpose + split: W[K][N] fp32 -> T[n][2K] interleaved (hi at k, lo at K+k)
__global__ void transpose_split(const float* __restrict__ W, bf16* __restrict__ T,
                                int K, int N) {
    __shared__ float t[32][33];
    int n0 = blockIdx.x * 32, k0 = blockIdx.y * 32;
    int tx = threadIdx.x, ty = threadIdx.y;
#pragma unroll
    for (int j = 0; j < 32; j += 8)
        t[ty + j][tx] = W[(size_t)(k0 + ty + j) * N + n0 + tx];
    __syncthreads();
#pragma unroll
    for (int j = 0; j < 32; j += 8) {
        float v = t[tx][ty + j];
        bf16 h = __float2bfloat16(v);
        size_t o = (size_t)(n0 + ty + j) * (2 * K) + k0 + tx;
        T[o]     = h;
        T[o + K] = __float2bfloat16(v - __bfloat162float(h));
    }
}

// elementwise split into interleaved rows of width 2K
__global__ void convert_split(const float* __restrict__ x, bf16* __restrict__ out,
                              size_t n4) {
    size_t i = (size_t)blockIdx.x * 256 + threadIdx.x;
    if (i >= n4) return;
    size_t row = i / (Cc / 4);
    int c4 = (int)(i % (Cc / 4));
    float4 v = ((const float4*)x)[i];
    bf16 h0 = __float2bfloat16(v.x), h1 = __float2bfloat16(v.y);
    bf16 h2 = __float2bfloat16(v.z), h3 = __float2bfloat16(v.w);
    size_t o = row * (2 * Cc) + c4 * 4;
    __nv_bfloat162 p0; p0.x = h0; p0.y = h1;
    __nv_bfloat162 p1; p1.x = h2; p1.y = h3;
    *(__nv_bfloat162*)&out[o]     = p0;
    *(__nv_bfloat162*)&out[o + 2] = p1;
    __nv_bfloat162 q0, q1;
    q0.x = __float2bfloat16(v.x - __bfloat162float(h0));
    q0.y = __float2bfloat16(v.y - __bfloat162float(h1));
    q1.x = __float2bfloat16(v.z - __bfloat162float(h2));
    q1.y = __float2bfloat16(v.w - __bfloat162float(h3));
    *(__nv_bfloat162*)&out[o + Cc]     = q0;
    *(__nv_bfloat162*)&out[o + Cc + 2] = q1;
}

__global__ void pool_split(const float* __restrict__ f, bf16* __restrict__ out) {
    int b = blockIdx.y;
    int c = blockIdx.x * 256 + threadIdx.x;
    const float* p = f + (size_t)b * HW * Cc + c;
    float s = 0.f;
#pragma unroll
    for (int i = 0; i < HW; i++) s += p[(size_t)i * Cc];
    s *= (1.0f / 49.0f);
    bf16 hi = __float2bfloat16(s);
    size_t o = (size_t)b * (2 * Cc) + c;
    out[o]      = hi;
    out[o + Cc] = __float2bfloat16(s - __bfloat162float(hi));
}

// ========================= mma.sync GEMM =====================================
// D[m][n] = sum_k A[m][k]*B[n][k]; A,B interleaved hi|lo (lo at +loA/+loB).
// Split-bf16 3-pass, fp32 accum. Tile 128x128, BK=32, cp.async double buffer,
// ldmatrix fragment loads. grid.z = head*nzk + kidx (head in {0,1}).
// EPI 0: fp32 partial at Cf + z*M*N.  EPI 1: bias+relu -> interleaved bf16 at
//        Cb + head*M*2N (row stride 2N, lo at +N).
#define ROWB 80
#define MATB (128*ROWB)
#define STGB (4*MATB)
#define SM_TOTAL (2*STGB)       // 81920

template<int EPI>
__global__ __launch_bounds__(256, 2)
void gemm_mma(const bf16* __restrict__ A0, const bf16* __restrict__ A1,
              const bf16* __restrict__ B0, const bf16* __restrict__ B1,
              const float* __restrict__ bias0, const float* __restrict__ bias1,
              float* __restrict__ Cf, bf16* __restrict__ Cb,
              int M, int N, int ldA, int ldB, int loA, int loB,
              int klen, int nzk) {
    extern __shared__ char smem[];
    const uint32_t sb = smem_u32(smem);
    const int tid = threadIdx.x;
    const int wid = tid >> 5;
    const int lid = tid & 31;
    const int wm = wid >> 2;
    const int wn = wid & 3;
    const int g = lid >> 2;
    const int t = lid & 3;
    const int bm = blockIdx.y * 128;
    const int bn = blockIdx.x * 128;
    const int z = blockIdx.z;
    const int head = z / nzk;
    const int kidx = z - head * nzk;
    const int kbeg = kidx * klen;
    const int nch = klen / 32;

    const bf16* A = (head ? A1 : A0) + (size_t)bm * ldA + kbeg;
    const bf16* B = (head ? B1 : B0) + (size_t)bn * ldB + kbeg;
    const float* bias = head ? bias1 : bias0;

    const int r0 = tid >> 2, c0 = tid & 3;

    float acc[4][4][4];
#pragma unroll
    for (int i = 0; i < 4; i++)
#pragma unroll
        for (int j = 0; j < 4; j++)
#pragma unroll
            for (int c = 0; c < 4; c++) acc[i][j][c] = 0.f;

    // prologue: chunk 0 -> stage 0
#pragma unroll
    for (int s = 0; s < 2; s++) {
        int r = r0 + s * 64;
        const bf16* pa = A + (size_t)r * ldA + c0 * 8;
        cp16(sb + 0*MATB + r*ROWB + c0*16, pa);
        cp16(sb + 1*MATB + r*ROWB + c0*16, pa + loA);
        const bf16* pb = B + (size_t)r * ldB + c0 * 8;
        cp16(sb + 2*MATB + r*ROWB + c0*16, pb);
        cp16(sb + 3*MATB + r*ROWB + c0*16, pb + loB);
    }
    CP_COMMIT();

    const uint32_t a_lm = (uint32_t)((wm*64 + (lid & 7) + ((lid >> 3) & 1) * 8) * ROWB
                                     + ((lid >> 4) & 1) * 16);
    const uint32_t b_lm = (uint32_t)((wn*32 + (lid & 7) + ((lid >> 4) & 1) * 8) * ROWB
                                     + ((lid >> 3) & 1) * 16);

    for (int ch = 0; ch < nch; ch++) {
        CP_WAIT0();
        __syncthreads();
        if (ch + 1 < nch) {
            const int k0 = (ch + 1) * 32;
            uint32_t st = sb + ((ch + 1) & 1) * STGB;
#pragma unroll
            for (int s = 0; s < 2; s++) {
                int r = r0 + s * 64;
                const bf16* pa = A + (size_t)r * ldA + k0 + c0 * 8;
                cp16(st + 0*MATB + r*ROWB + c0*16, pa);
                cp16(st + 1*MATB + r*ROWB + c0*16, pa + loA);
                const bf16* pb = B + (size_t)r * ldB + k0 + c0 * 8;
                cp16(st + 2*MATB + r*ROWB + c0*16, pb);
                cp16(st + 3*MATB + r*ROWB + c0*16, pb + loB);
            }
            CP_COMMIT();
        }
        const uint32_t st = sb + (ch & 1) * STGB;
#pragma unroll
        for (int ks = 0; ks < 2; ks++) {
            uint32_t ah[4][4], al[4][4], bh[4][2], bl[4][2];
#pragma unroll
            for (int i = 0; i < 4; i++) {
                uint32_t aa = st + a_lm + i * (16 * ROWB) + ks * 32;
                LDMX4(ah[i][0], ah[i][1], ah[i][2], ah[i][3], aa);
                LDMX4(al[i][0], al[i][1], al[i][2], al[i][3], aa + MATB);
            }
#pragma unroll
            for (int jp = 0; jp < 2; jp++) {
                uint32_t bb = st + 2*MATB + b_lm + jp * (16 * ROWB) + ks * 32;
                LDMX4(bh[2*jp][0], bh[2*jp][1], bh[2*jp+1][0], bh[2*jp+1][1], bb);
                LDMX4(bl[2*jp][0], bl[2*jp][1], bl[2*jp+1][0], bl[2*jp+1][1], bb + MATB);
            }
#pragma unroll
            for (int i = 0; i < 4; i++)
#pragma unroll
                for (int j = 0; j < 4; j++) {
                    mma16816(acc[i][j], ah[i], bh[j]);
                    mma16816(acc[i][j], ah[i], bl[j]);
                    mma16816(acc[i][j], al[i], bh[j]);
                }
        }
        __syncthreads();
    }

    // ---- epilogue ----
#pragma unroll
    for (int i = 0; i < 4; i++) {
        int row0 = bm + wm*64 + i*16 + g;
#pragma unroll
        for (int j = 0; j < 4; j++) {
            int col = bn + wn*32 + j*8 + 2*t;
            float b0 = 0.f, b1 = 0.f;
            if (bias) { b0 = bias[col]; b1 = bias[col + 1]; }
#pragma unroll
            for (int h = 0; h < 2; h++) {
                int row = row0 + h*8;
                float v0 = acc[i][j][2*h]     + b0;
                float v1 = acc[i][j][2*h + 1] + b1;
                if (EPI == 1) {
                    v0 = fmaxf(v0, 0.f); v1 = fmaxf(v1, 0.f);
                    bf16 h0 = __float2bfloat16(v0), h1 = __float2bfloat16(v1);
                    size_t o = (size_t)head * M * (2 * N) + (size_t)row * (2 * N) + col;
                    __nv_bfloat162 ph; ph.x = h0; ph.y = h1;
                    *(__nv_bfloat162*)&Cb[o] = ph;
                    __nv_bfloat162 pl;
                    pl.x = __float2bfloat16(v0 - __bfloat162float(h0));
                    pl.y = __float2bfloat16(v1 - __bfloat162float(h1));
                    *(__nv_bfloat162*)&Cb[o + N] = pl;
                } else {
                    size_t o = (size_t)z * M * N + (size_t)row * N + col;
                    float2 fv; fv.x = v0; fv.y = v1;
                    *(float2*)&Cf[o] = fv;
                }
            }
        }
    }
}

// split-K reduce. EPI 0: fp32+bias -> Cf. EPI 1: bias+relu -> interleaved bf16 Cb.
template<int EPI>
__global__ void reduce_split(const float* __restrict__ part, const float* __restrict__ bias,
                             float* __restrict__ Cf, bf16* __restrict__ Cb,
                             int S, size_t MN, int N) {
    size_t i4 = (size_t)blockIdx.x * 256 + threadIdx.x;
    if (i4 * 4 >= MN) return;
    float4 a = {0.f, 0.f, 0.f, 0.f};
    for (int s = 0; s < S; s++) {
        float4 v = *(const float4*)(part + s * MN + i4 * 4);
        a.x += v.x; a.y += v.y; a.z += v.z; a.w += v.w;
    }
    size_t base = i4 * 4;
    int n = (int)(base % N);
    a.x += bias[n]; a.y += bias[n+1]; a.z += bias[n+2]; a.w += bias[n+3];
    if (EPI == 1) {
        a.x = fmaxf(a.x, 0.f); a.y = fmaxf(a.y, 0.f);
        a.z = fmaxf(a.z, 0.f); a.w = fmaxf(a.w, 0.f);
        size_t row = base / N;
        size_t o = row * (2 * (size_t)N) + n;
        bf16 h0 = __float2bfloat16(a.x), h1 = __float2bfloat16(a.y);
        bf16 h2 = __float2bfloat16(a.z), h3 = __float2bfloat16(a.w);
        __nv_bfloat162 p0; p0.x = h0; p0.y = h1;
        __nv_bfloat162 p1; p1.x = h2; p1.y = h3;
        *(__nv_bfloat162*)&Cb[o]     = p0;
        *(__nv_bfloat162*)&Cb[o + 2] = p1;
        __nv_bfloat162 q0, q1;
        q0.x = __float2bfloat16(a.x - __bfloat162float(h0));
        q0.y = __float2bfloat16(a.y - __bfloat162float(h1));
        q1.x = __float2bfloat16(a.z - __bfloat162float(h2));
        q1.y = __float2bfloat16(a.w - __bfloat162float(h3));
        *(__nv_bfloat162*)&Cb[o + N]     = q0;
        *(__nv_bfloat162*)&Cb[o + N + 2] = q1;
    } else {
        *(float4*)&Cf[base] = a;
    }
}

// ========================= small kernels =====================================
__global__ void l2norm_kernel(float* __restrict__ x, int rows) {
    int row = blockIdx.x * 8 + threadIdx.y;
    if (row >= rows) return;
    float* p = x + (size_t)row * De;
    int lane = threadIdx.x;
    float4 v = *(float4*)(p + lane * 4);
    float ss = v.x*v.x + v.y*v.y + v.z*v.z + v.w*v.w;
#pragma unroll
    for (int o = 16; o; o >>= 1) ss += __shfl_xor_sync(0xFFFFFFFFu, ss, o);
    float r = 1.0f / sqrtf(fmaxf(ss, 1e-12f));
    v.x *= r; v.y *= r; v.z *= r; v.w *= r;
    *(float4*)(p + lane * 4) = v;
}

// l2norm + interleaved bf16 hi|lo copy (row stride 2De)
__global__ void l2norm_split(float* __restrict__ x, bf16* __restrict__ m, int rows) {
    int row = blockIdx.x * 8 + threadIdx.y;
    if (row >= rows) return;
    float* p = x + (size_t)row * De;
    int lane = threadIdx.x;
    float4 v = *(float4*)(p + lane * 4);
    float ss = v.x*v.x + v.y*v.y + v.z*v.z + v.w*v.w;
#pragma unroll
    for (int o = 16; o; o >>= 1) ss += __shfl_xor_sync(0xFFFFFFFFu, ss, o);
    float r = 1.0f / sqrtf(fmaxf(ss, 1e-12f));
    v.x *= r; v.y *= r; v.z *= r; v.w *= r;
    *(float4*)(p + lane * 4) = v;
    size_t o = (size_t)row * (2 * De) + lane * 4;
    bf16 h0 = __float2bfloat16(v.x), h1 = __float2bfloat16(v.y);
    bf16 h2 = __float2bfloat16(v.z), h3 = __float2bfloat16(v.w);
    __nv_bfloat162 p0; p0.x = h0; p0.y = h1;
    __nv_bfloat162 p1; p1.x = h2; p1.y = h3;
    *(__nv_bfloat162*)&m[o]     = p0;
    *(__nv_bfloat162*)&m[o + 2] = p1;
    __nv_bfloat162 q0, q1;
    q0.x = __float2bfloat16(v.x - __bfloat162float(h0));
    q0.y = __float2bfloat16(v.y - __bfloat162float(h1));
    q1.x = __float2bfloat16(v.z - __bfloat162float(h2));
    q1.y = __float2bfloat16(v.w - __bfloat162float(h3));
    *(__nv_bfloat162*)&m[o + De]     = q0;
    *(__nv_bfloat162*)&m[o + De + 2] = q1;
}

__global__ void lg_kernel(const float* __restrict__ qg, const float* __restrict__ kg,
                          float* __restrict__ out) {
    int row = blockIdx.x;
    __shared__ float qs[De];
    __shared__ float red[128];
    int t = threadIdx.x;
    qs[t] = qg[(size_t)row * De + t];
    __syncthreads();
    const float* kp = kg + (size_t)t * De;
    float dot = 0.f;
#pragma unroll 8
    for (int c = 0; c < De; c++) dot = fmaf(qs[c], kp[c], dot);
    float logit = dot * INV_TAU;          // |logit| <= 5: no max rescale needed
    red[t] = __expf(logit); __syncthreads();
    for (int s = 64; s; s >>= 1) { if (t < s) red[t] += red[t + s]; __syncthreads(); }
    float lse = logf(red[0]);
    if (t == row) out[row] = lse - logit;
}

__global__ void match_kernel(const float* __restrict__ qd, const float* __restrict__ kd,
                             bf16* __restrict__ mt, float* __restrict__ pos) {
    int row = blockIdx.x;
    int b = row / HW;
    __shared__ float qs[De];
    __shared__ float dots[64];
    __shared__ int   s_idx;
    __shared__ float s_val;
    int t = threadIdx.x;
    qs[t] = qd[(size_t)row * De + t];
    __syncthreads();
    if (t < HW) {
        const float* kp = kd + (size_t)(b * HW + t) * De;
        float d = 0.f;
#pragma unroll 8
        for (int c = 0; c < De; c++) d = fmaf(qs[c], kp[c], d);
        dots[t] = d;
    }
    __syncthreads();
    if (t == 0) {
        float bv = dots[0]; int bi = 0;
        for (int j = 1; j < HW; j++)
            if (dots[j] > bv) { bv = dots[j]; bi = j; }
        s_idx = bi; s_val = bv;
    }
    __syncthreads();
    float v = kd[(size_t)(b * HW + s_idx) * De + t];
    bf16 h = __float2bfloat16(v);
    size_t o = (size_t)row * (2 * De) + t;
    mt[o]      = h;
    mt[o + De] = __float2bfloat16(v - __bfloat162float(h));
    if (t == 0) pos[row] = s_val;
}

// fast row LSE: logits = 5*dot of unit vectors, bounded by 5 -> no max pass
__global__ void row_lse_kernel(const float* __restrict__ S, const float* __restrict__ pos,
                               float* __restrict__ out, int N) {
    int row = blockIdx.x;
    const float4* p = (const float4*)(S + (size_t)row * N);
    int t = threadIdx.x;
    float s = 0.f;
    for (int j = t; j < N / 4; j += 256) {
        float4 v = p[j];
        s += __expf(v.x * INV_TAU) + __expf(v.y * INV_TAU)
           + __expf(v.z * INV_TAU) + __expf(v.w * INV_TAU);
    }
    __shared__ float ssh[256];
    ssh[t] = s; __syncthreads();
    for (int o = 128; o; o >>= 1) {
        if (t < o) ssh[t] += ssh[t + o];
        __syncthreads();
    }
    if (t == 0) out[row] = logf(ssh[0]) - pos[row] * INV_TAU;
}

__global__ void final_kernel(const float* __restrict__ lg, const float* __restrict__ ld,
                             float* __restrict__ out) {
    int t = threadIdx.x;
    float s1 = 0.f, s2 = 0.f;
    if (t < Bn) s1 = lg[t];
    for (int j = t; j < Nrow; j += 256) s2 += ld[j];
    __shared__ float r1[256], r2[256];
    r1[t] = s1; r2[t] = s2; __syncthreads();
    for (int o = 128; o; o >>= 1) {
        if (t < o) { r1[t] += r1[t + o]; r2[t] += r2[t + o]; }
        __syncthreads();
    }
    if (t == 0) out[0] = 0.5f * (r1[0] / (float)Bn) + 0.5f * (r2[0] / (float)Nrow);
}

// ========================= host orchestration ================================
extern "C" void kernel_launch(void* const* d_in, const int* in_sizes, int n_in,
                              void* d_out, int out_size) {
    const float* feat_q = (const float*)d_in[0];
    const float* feat_k = (const float*)d_in[1];
    const float* Wg1  = (const float*)d_in[2];   const float* bg1 = (const float*)d_in[3];
    const float* Wg2  = (const float*)d_in[4];   const float* bg2 = (const float*)d_in[5];
    const float* Wd1  = (const float*)d_in[6];   const float* bd1 = (const float*)d_in[7];
    const float* Wd2  = (const float*)d_in[8];   const float* bd2 = (const float*)d_in[9];
    const float* mWg1 = (const float*)d_in[10];  const float* mbg1 = (const float*)d_in[11];
    const float* mWg2 = (const float*)d_in[12];  const float* mbg2 = (const float*)d_in[13];
    const float* mWd1 = (const float*)d_in[14];  const float* mbd1 = (const float*)d_in[15];
    const float* mWd2 = (const float*)d_in[16];  const float* mbd2 = (const float*)d_in[17];
    float* out = (float*)d_out;

    cudaFuncSetAttribute(gemm_mma<0>, cudaFuncAttributeMaxDynamicSharedMemorySize, SM_TOTAL);
    cudaFuncSetAttribute(gemm_mma<1>, cudaFuncAttributeMaxDynamicSharedMemorySize, SM_TOTAL);

#define SYM(p, s) cudaGetSymbolAddress((void**)&p, s)
    bf16 *Wd1T, *mWd1T, *Wg1T, *mWg1T, *Wg2T, *Wd2T, *mWg2T, *mWd2T;
    bf16 *Aq, *Ak, *pq, *pk, *gh, *hid, *qdm, *mt;
    float *part, *qg, *kg, *qd, *kd, *S, *pos, *lg, *ld;
    SYM(Wd1T, g_Wd1T); SYM(mWd1T, g_mWd1T); SYM(Wg1T, g_Wg1T); SYM(mWg1T, g_mWg1T);
    SYM(Wg2T, g_Wg2T); SYM(Wd2T, g_Wd2T); SYM(mWg2T, g_mWg2T); SYM(mWd2T, g_mWd2T);
    SYM(Aq, g_Aq); SYM(Ak, g_Ak); SYM(pq, g_pq); SYM(pk, g_pk);
    SYM(gh, g_gh); SYM(hid, g_hid); SYM(qdm, g_qdm); SYM(mt, g_mt);
    SYM(part, g_part); SYM(qg, g_qg); SYM(kg, g_kg); SYM(qd, g_qd); SYM(kd, g_kd);
    SYM(S, g_S); SYM(pos, g_pos); SYM(lg, g_lg); SYM(ld, g_ld);
#undef SYM

    // ---- pre-pass ----
    dim3 tb(32, 8);
    transpose_split<<<dim3(Dh/32, Cc/32), tb>>>(Wd1,  Wd1T,  Cc, Dh);
    transpose_split<<<dim3(Dh/32, Cc/32), tb>>>(mWd1, mWd1T, Cc, Dh);
    transpose_split<<<dim3(Dh/32, Cc/32), tb>>>(Wg1,  Wg1T,  Cc, Dh);
    transpose_split<<<dim3(Dh/32, Cc/32), tb>>>(mWg1, mWg1T, Cc, Dh);
    transpose_split<<<dim3(De/32, Dh/32), tb>>>(Wg2,  Wg2T,  Dh, De);
    transpose_split<<<dim3(De/32, Dh/32), tb>>>(Wd2,  Wd2T,  Dh, De);
    transpose_split<<<dim3(De/32, Dh/32), tb>>>(mWg2, mWg2T, Dh, De);
    transpose_split<<<dim3(De/32, Dh/32), tb>>>(mWd2, mWd2T, Dh, De);

    size_t featN4 = (size_t)Nrow * Cc / 4;
    convert_split<<<(unsigned)((featN4 + 255) / 256), 256>>>(feat_q, Aq, featN4);
    convert_split<<<(unsigned)((featN4 + 255) / 256), 256>>>(feat_k, Ak, featN4);
    pool_split<<<dim3(Cc/256, Bn), 256>>>(feat_q, pq);
    pool_split<<<dim3(Cc/256, Bn), 256>>>(feat_k, pk);

    // ---- global head L1 (q+k merged, split-K 8) ----
    gemm_mma<0><<<dim3(Dh/128, 1, 16), 256, SM_TOTAL>>>(pq, pk, Wg1T, mWg1T,
        nullptr, nullptr, part, nullptr, Bn, Dh, 2*Cc, 2*Cc, Cc, Cc, Cc/8, 8);
    reduce_split<1><<<(Bn*Dh/4 + 255)/256, 256>>>(part, bg1, nullptr, gh, 8, (size_t)Bn*Dh, Dh);
    reduce_split<1><<<(Bn*Dh/4 + 255)/256, 256>>>(part + 8*(size_t)Bn*Dh, mbg1, nullptr,
        gh + (size_t)Bn*2*Dh, 8, (size_t)Bn*Dh, Dh);
    // ---- global head L2 (merged, split-K 16) ----
    gemm_mma<0><<<dim3(1, 1, 32), 256, SM_TOTAL>>>(gh, gh + (size_t)Bn*2*Dh, Wg2T, mWg2T,
        nullptr, nullptr, part, nullptr, Bn, De, 2*Dh, 2*Dh, Dh, Dh, Dh/16, 16);
    reduce_split<0><<<(Bn*De/4 + 255)/256, 256>>>(part, bg2, qg, nullptr, 16, (size_t)Bn*De, De);
    reduce_split<0><<<(Bn*De/4 + 255)/256, 256>>>(part + 16*(size_t)Bn*De, mbg2, kg, nullptr,
        16, (size_t)Bn*De, De);

    l2norm_kernel<<<(Bn + 7)/8, dim3(32, 8)>>>(qg, Bn);
    l2norm_kernel<<<(Bn + 7)/8, dim3(32, 8)>>>(kg, Bn);
    lg_kernel<<<Bn, 128>>>(qg, kg, lg);

    // ---- dense head L1 (q+k merged) ----
    gemm_mma<1><<<dim3(Dh/128, Nrow/128, 2), 256, SM_TOTAL>>>(Aq, Ak, Wd1T, mWd1T,
        bd1, mbd1, nullptr, hid, Nrow, Dh, 2*Cc, 2*Cc, Cc, Cc, Cc, 1);
    // ---- dense head L2 (merged, split-K 4) ----
    gemm_mma<0><<<dim3(1, Nrow/128, 8), 256, SM_TOTAL>>>(hid, hid + (size_t)Nrow*2*Dh,
        Wd2T, mWd2T, nullptr, nullptr, part, nullptr, Nrow, De, 2*Dh, 2*Dh, Dh, Dh, Dh/4, 4);
    reduce_split<0><<<(Nrow*De/4 + 255)/256, 256>>>(part, bd2, qd, nullptr, 4, (size_t)Nrow*De, De);
    reduce_split<0><<<(Nrow*De/4 + 255)/256, 256>>>(part + 4*(size_t)Nrow*De, mbd2, kd, nullptr,
        4, (size_t)Nrow*De, De);

    l2norm_split<<<Nrow/8, dim3(32, 8)>>>(qd, qdm, Nrow);
    l2norm_kernel<<<Nrow/8, dim3(32, 8)>>>(kd, Nrow);

    // ---- matching + dense InfoNCE ----
    match_kernel<<<Nrow, 128>>>(qd, kd, mt, pos);
    gemm_mma<0><<<dim3(Nrow/128, Nrow/128, 1), 256, SM_TOTAL>>>(qdm, qdm, mt, mt,
        nullptr, nullptr, S, nullptr, Nrow, Nrow, 2*De, 2*De, De, De, De, 1);
    row_lse_kernel<<<Nrow, 256>>>(S, pos, ld, Nrow);

    final_kernel<<<1, 256>>>(lg, ld, out);
}

// round 5
// speedup vs baseline: 3.8428x; 1.0585x over previous
#include <cuda_runtime.h>
#include <cuda_bf16.h>
#include <math.h>
#include <stdint.h>

#define Bn   128
#define HW   49
#define Cc   2048
#define Dh   2048
#define De   128
#define Nrow (Bn*HW)          // 6272
#define NTILE 49              // Nrow/128
#define INV_TAU 5.0f

typedef __nv_bfloat16 bf16;

// ========================= PTX helpers (compute_103-safe) ====================
__device__ __forceinline__ uint32_t smem_u32(const void* p) {
    uint32_t a;
    asm("{ .reg .u64 t; cvta.to.shared.u64 t, %1; cvt.u32.u64 %0, t; }" : "=r"(a) : "l"(p));
    return a;
}
__device__ __forceinline__ void cp16(uint32_t dst, const void* src) {
    asm volatile("cp.async.cg.shared.global [%0], [%1], 16;" :: "r"(dst), "l"(src));
}
#define CP_COMMIT() asm volatile("cp.async.commit_group;" ::: "memory")
#define CP_WAIT0()  asm volatile("cp.async.wait_group 0;" ::: "memory")
#define LDMX4(r0, r1, r2, r3, addr)                                            \
    asm volatile("ldmatrix.sync.aligned.m8n8.x4.shared.b16 {%0,%1,%2,%3}, [%4];" \
        : "=r"(r0), "=r"(r1), "=r"(r2), "=r"(r3) : "r"(addr))

__device__ __forceinline__ void mma16816(float* c, const uint32_t* a, const uint32_t* b) {
    asm volatile("mma.sync.aligned.m16n8k16.row.col.f32.bf16.bf16.f32 "
        "{%0,%1,%2,%3}, {%4,%5,%6,%7}, {%8,%9}, {%0,%1,%2,%3};"
        : "+f"(c[0]), "+f"(c[1]), "+f"(c[2]), "+f"(c[3])
        : "r"(a[0]), "r"(a[1]), "r"(a[2]), "r"(a[3]), "r"(b[0]), "r"(b[1]));
}

// ========================= scratch buffers ===================================
// Interleaved hi|lo layout: row stride 2K, lo at +K within the row.
__device__ __align__(256) bf16 g_Wd1T[(size_t)Dh*2*Cc];
__device__ __align__(256) bf16 g_mWd1T[(size_t)Dh*2*Cc];
__device__ __align__(256) bf16 g_Wg1T[(size_t)Dh*2*Cc];
__device__ __align__(256) bf16 g_mWg1T[(size_t)Dh*2*Cc];
__device__ __align__(256) bf16 g_Wg2T[De*2*Dh], g_Wd2T[De*2*Dh];
__device__ __align__(256) bf16 g_mWg2T[De*2*Dh], g_mWd2T[De*2*Dh];
__device__ __align__(256) bf16 g_Aq[(size_t)Nrow*2*Cc], g_Ak[(size_t)Nrow*2*Cc];
__device__ __align__(256) bf16 g_pq[Bn*2*Cc], g_pk[Bn*2*Cc];
__device__ __align__(256) bf16 g_gh[2*(size_t)Bn*2*Dh];
__device__ __align__(256) bf16 g_hid[2*(size_t)Nrow*2*Dh];
__device__ __align__(256) bf16 g_qdm[Nrow*2*De], g_mt[Nrow*2*De];
__device__ __align__(256) float g_part[8*(size_t)Nrow*De];
__device__ __align__(256) float g_Spart[(size_t)NTILE*Nrow];
__device__ float g_qg[Bn*De], g_kg[Bn*De];
__device__ float g_qd[Nrow*De], g_kd[Nrow*De];
__device__ float g_pos[Nrow], g_lg[Bn], g_ld[Nrow];

// ========================= pre-pass kernels ==================================
// transpose + split: W[K][N] fp32 -> T[n][2K] interleaved. Tile 64(K) x 32(N).
__global__ void transpose_split(const float* __restrict__ W, bf16* __restrict__ T,
                                int K, int N) {
    __shared__ float t[32][65];                 // [n][k]
    int n0 = blockIdx.x * 32, k0 = blockIdx.y * 64;
    int tx = threadIdx.x, ty = threadIdx.y;
#pragma unroll
    for (int r = 0; r < 64; r += 8)
        t[tx][r + ty] = W[(size_t)(k0 + r + ty) * N + n0 + tx];
    __syncthreads();
#pragma unroll
    for (int j = 0; j < 4; j++) {
        int nl = ty + j * 8;
        float v0 = t[nl][2 * tx], v1 = t[nl][2 * tx + 1];
        bf16 h0 = __float2bfloat16(v0), h1 = __float2bfloat16(v1);
        size_t o = (size_t)(n0 + nl) * (2 * K) + k0 + 2 * tx;
        __nv_bfloat162 ph; ph.x = h0; ph.y = h1;
        *(__nv_bfloat162*)&T[o] = ph;
        __nv_bfloat162 pl;
        pl.x = __float2bfloat16(v0 - __bfloat162float(h0));
        pl.y = __float2bfloat16(v1 - __bfloat162float(h1));
        *(__nv_bfloat162*)&T[o + K] = pl;
    }
}

// fused: per-pixel split + mean-pool split (one read of feat)
__global__ void feat_prep(const float* __restrict__ f, bf16* __restrict__ A,
                          bf16* __restrict__ pool) {
    int b = blockIdx.y;
    int c = blockIdx.x * 256 + threadIdx.x;
    const float* p = f + (size_t)b * HW * Cc + c;
    float s = 0.f;
#pragma unroll
    for (int i = 0; i < HW; i++) {
        float v = p[(size_t)i * Cc];
        s += v;
        bf16 h = __float2bfloat16(v);
        size_t o = ((size_t)b * HW + i) * (2 * Cc) + c;
        A[o]      = h;
        A[o + Cc] = __float2bfloat16(v - __bfloat162float(h));
    }
    s *= (1.0f / 49.0f);
    bf16 hi = __float2bfloat16(s);
    size_t o = (size_t)b * (2 * Cc) + c;
    pool[o]      = hi;
    pool[o + Cc] = __float2bfloat16(s - __bfloat162float(hi));
}

// ========================= mma.sync GEMM =====================================
// D[m][n] = sum_k A[m][k]*B[n][k]; A,B interleaved hi|lo (lo at +loA/+loB).
// Split-bf16 3-pass, fp32 accum. 128x128 tile, BK=32, cp.async double buffer.
// grid.z = head*nzk + kidx; uneven split-K via (nbC base chunks, remC).
// EPI 0: fp32 partial at Cf + z*M*N
// EPI 1: bias+relu -> interleaved bf16 at Cb + head*M*2N
// EPI 2: exp-rowsum -> Cf[blockIdx.x*M + row]  (S-GEMM fused LSE partial)
#define ROWB 80
#define MATB (128*ROWB)
#define STGB (4*MATB)
#define SM_TOTAL (2*STGB)       // 81920

template<int EPI>
__global__ __launch_bounds__(256, 2)
void gemm_mma(const bf16* __restrict__ A0, const bf16* __restrict__ A1,
              const bf16* __restrict__ B0, const bf16* __restrict__ B1,
              const float* __restrict__ bias0, const float* __restrict__ bias1,
              float* __restrict__ Cf, bf16* __restrict__ Cb,
              int M, int N, int ldA, int ldB, int loA, int loB,
              int nbC, int remC, int nzk) {
    extern __shared__ char smem[];
    const uint32_t sb = smem_u32(smem);
    const int tid = threadIdx.x;
    const int wid = tid >> 5;
    const int lid = tid & 31;
    const int wm = wid >> 2;
    const int wn = wid & 3;
    const int g = lid >> 2;
    const int t = lid & 3;
    const int bm = blockIdx.y * 128;
    const int bn = blockIdx.x * 128;
    const int z = blockIdx.z;
    const int head = z / nzk;
    const int kidx = z - head * nzk;
    const int kbeg = (kidx * nbC + min(kidx, remC)) * 32;
    const int nch = nbC + (kidx < remC ? 1 : 0);

    const bf16* A = (head ? A1 : A0) + (size_t)bm * ldA + kbeg;
    const bf16* B = (head ? B1 : B0) + (size_t)bn * ldB + kbeg;
    const float* bias = head ? bias1 : bias0;

    const int r0 = tid >> 2, c0 = tid & 3;

    float acc[4][4][4];
#pragma unroll
    for (int i = 0; i < 4; i++)
#pragma unroll
        for (int j = 0; j < 4; j++)
#pragma unroll
            for (int c = 0; c < 4; c++) acc[i][j][c] = 0.f;

    // prologue: chunk 0 -> stage 0
#pragma unroll
    for (int s = 0; s < 2; s++) {
        int r = r0 + s * 64;
        const bf16* pa = A + (size_t)r * ldA + c0 * 8;
        cp16(sb + 0*MATB + r*ROWB + c0*16, pa);
        cp16(sb + 1*MATB + r*ROWB + c0*16, pa + loA);
        const bf16* pb = B + (size_t)r * ldB + c0 * 8;
        cp16(sb + 2*MATB + r*ROWB + c0*16, pb);
        cp16(sb + 3*MATB + r*ROWB + c0*16, pb + loB);
    }
    CP_COMMIT();

    const uint32_t a_lm = (uint32_t)((wm*64 + (lid & 7) + ((lid >> 3) & 1) * 8) * ROWB
                                     + ((lid >> 4) & 1) * 16);
    const uint32_t b_lm = (uint32_t)((wn*32 + (lid & 7) + ((lid >> 4) & 1) * 8) * ROWB
                                     + ((lid >> 3) & 1) * 16);

    for (int ch = 0; ch < nch; ch++) {
        CP_WAIT0();
        __syncthreads();
        if (ch + 1 < nch) {
            const int k0 = (ch + 1) * 32;
            uint32_t st = sb + ((ch + 1) & 1) * STGB;
#pragma unroll
            for (int s = 0; s < 2; s++) {
                int r = r0 + s * 64;
                const bf16* pa = A + (size_t)r * ldA + k0 + c0 * 8;
                cp16(st + 0*MATB + r*ROWB + c0*16, pa);
                cp16(st + 1*MATB + r*ROWB + c0*16, pa + loA);
                const bf16* pb = B + (size_t)r * ldB + k0 + c0 * 8;
                cp16(st + 2*MATB + r*ROWB + c0*16, pb);
                cp16(st + 3*MATB + r*ROWB + c0*16, pb + loB);
            }
            CP_COMMIT();
        }
        const uint32_t st = sb + (ch & 1) * STGB;
#pragma unroll
        for (int ks = 0; ks < 2; ks++) {
            uint32_t ah[4][4], al[4][4];
#pragma unroll
            for (int i = 0; i < 4; i++) {
                uint32_t aa = st + a_lm + i * (16 * ROWB) + ks * 32;
                LDMX4(ah[i][0], ah[i][1], ah[i][2], ah[i][3], aa);
                LDMX4(al[i][0], al[i][1], al[i][2], al[i][3], aa + MATB);
            }
            // j-split: only 2 of 4 b-fragment pairs live at a time (reg pressure)
#pragma unroll
            for (int jp = 0; jp < 2; jp++) {
                uint32_t bh[2][2], bl[2][2];
                uint32_t bb = st + 2*MATB + b_lm + jp * (16 * ROWB) + ks * 32;
                LDMX4(bh[0][0], bh[0][1], bh[1][0], bh[1][1], bb);
                LDMX4(bl[0][0], bl[0][1], bl[1][0], bl[1][1], bb + MATB);
#pragma unroll
                for (int i = 0; i < 4; i++)
#pragma unroll
                    for (int jj = 0; jj < 2; jj++) {
                        float* a = acc[i][jp*2 + jj];
                        mma16816(a, ah[i], bh[jj]);
                        mma16816(a, ah[i], bl[jj]);
                        mma16816(a, al[i], bh[jj]);
                    }
            }
        }
        __syncthreads();
    }

    // ---- epilogue ----
    if (EPI == 2) {
        // fused exp row-sum: Spart[bx*M + row] = sum_cols exp(5*acc)
        float rs[8];
#pragma unroll
        for (int i = 0; i < 4; i++)
#pragma unroll
            for (int h = 0; h < 2; h++) {
                float s = 0.f;
#pragma unroll
                for (int j = 0; j < 4; j++)
                    s += __expf(acc[i][j][2*h] * INV_TAU)
                       + __expf(acc[i][j][2*h + 1] * INV_TAU);
                s += __shfl_xor_sync(0xFFFFFFFFu, s, 1);
                s += __shfl_xor_sync(0xFFFFFFFFu, s, 2);
                rs[i*2 + h] = s;
            }
        float* sm = (float*)smem;
        __syncthreads();
        if (t == 0) {
#pragma unroll
            for (int idx = 0; idx < 8; idx++) {
                int i = idx >> 1, h = idx & 1;
                int row = wm*64 + i*16 + g + h*8;
                sm[row*4 + wn] = rs[idx];
            }
        }
        __syncthreads();
        if (tid < 128) {
            float tot = sm[tid*4+0] + sm[tid*4+1] + sm[tid*4+2] + sm[tid*4+3];
            Cf[(size_t)blockIdx.x * M + bm + tid] = tot;
        }
        return;
    }
#pragma unroll
    for (int i = 0; i < 4; i++) {
        int row0 = bm + wm*64 + i*16 + g;
#pragma unroll
        for (int j = 0; j < 4; j++) {
            int col = bn + wn*32 + j*8 + 2*t;
            float b0 = 0.f, b1 = 0.f;
            if (bias) { b0 = bias[col]; b1 = bias[col + 1]; }
#pragma unroll
            for (int h = 0; h < 2; h++) {
                int row = row0 + h*8;
                float v0 = acc[i][j][2*h]     + b0;
                float v1 = acc[i][j][2*h + 1] + b1;
                if (EPI == 1) {
                    v0 = fmaxf(v0, 0.f); v1 = fmaxf(v1, 0.f);
                    bf16 h0 = __float2bfloat16(v0), h1 = __float2bfloat16(v1);
                    size_t o = (size_t)head * M * (2 * N) + (size_t)row * (2 * N) + col;
                    __nv_bfloat162 ph; ph.x = h0; ph.y = h1;
                    *(__nv_bfloat162*)&Cb[o] = ph;
                    __nv_bfloat162 pl;
                    pl.x = __float2bfloat16(v0 - __bfloat162float(h0));
                    pl.y = __float2bfloat16(v1 - __bfloat162float(h1));
                    *(__nv_bfloat162*)&Cb[o + N] = pl;
                } else {
                    size_t o = (size_t)z * M * N + (size_t)row * N + col;
                    float2 fv; fv.x = v0; fv.y = v1;
                    *(float2*)&Cf[o] = fv;
                }
            }
        }
    }
}

// split-K reduce. EPI 0: fp32+bias -> Cf. EPI 1: bias+relu -> interleaved bf16 Cb.
template<int EPI>
__global__ void reduce_split(const float* __restrict__ part, const float* __restrict__ bias,
                             float* __restrict__ Cf, bf16* __restrict__ Cb,
                             int S, size_t MN, int N) {
    size_t i4 = (size_t)blockIdx.x * 256 + threadIdx.x;
    if (i4 * 4 >= MN) return;
    float4 a = {0.f, 0.f, 0.f, 0.f};
    for (int s = 0; s < S; s++) {
        float4 v = *(const float4*)(part + s * MN + i4 * 4);
        a.x += v.x; a.y += v.y; a.z += v.z; a.w += v.w;
    }
    size_t base = i4 * 4;
    int n = (int)(base % N);
    a.x += bias[n]; a.y += bias[n+1]; a.z += bias[n+2]; a.w += bias[n+3];
    if (EPI == 1) {
        a.x = fmaxf(a.x, 0.f); a.y = fmaxf(a.y, 0.f);
        a.z = fmaxf(a.z, 0.f); a.w = fmaxf(a.w, 0.f);
        size_t row = base / N;
        size_t o = row * (2 * (size_t)N) + n;
        bf16 h0 = __float2bfloat16(a.x), h1 = __float2bfloat16(a.y);
        bf16 h2 = __float2bfloat16(a.z), h3 = __float2bfloat16(a.w);
        __nv_bfloat162 p0; p0.x = h0; p0.y = h1;
        __nv_bfloat162 p1; p1.x = h2; p1.y = h3;
        *(__nv_bfloat162*)&Cb[o]     = p0;
        *(__nv_bfloat162*)&Cb[o + 2] = p1;
        __nv_bfloat162 q0, q1;
        q0.x = __float2bfloat16(a.x - __bfloat162float(h0));
        q0.y = __float2bfloat16(a.y - __bfloat162float(h1));
        q1.x = __float2bfloat16(a.z - __bfloat162float(h2));
        q1.y = __float2bfloat16(a.w - __bfloat162float(h3));
        *(__nv_bfloat162*)&Cb[o + N]     = q0;
        *(__nv_bfloat162*)&Cb[o + N + 2] = q1;
    } else {
        *(float4*)&Cf[base] = a;
    }
}

// ========================= small kernels =====================================
__global__ void l2norm_kernel(float* __restrict__ x, int rows) {
    int row = blockIdx.x * 8 + threadIdx.y;
    if (row >= rows) return;
    float* p = x + (size_t)row * De;
    int lane = threadIdx.x;
    float4 v = *(float4*)(p + lane * 4);
    float ss = v.x*v.x + v.y*v.y + v.z*v.z + v.w*v.w;
#pragma unroll
    for (int o = 16; o; o >>= 1) ss += __shfl_xor_sync(0xFFFFFFFFu, ss, o);
    float r = 1.0f / sqrtf(fmaxf(ss, 1e-12f));
    v.x *= r; v.y *= r; v.z *= r; v.w *= r;
    *(float4*)(p + lane * 4) = v;
}

__global__ void l2norm_split(float* __restrict__ x, bf16* __restrict__ m, int rows) {
    int row = blockIdx.x * 8 + threadIdx.y;
    if (row >= rows) return;
    float* p = x + (size_t)row * De;
    int lane = threadIdx.x;
    float4 v = *(float4*)(p + lane * 4);
    float ss = v.x*v.x + v.y*v.y + v.z*v.z + v.w*v.w;
#pragma unroll
    for (int o = 16; o; o >>= 1) ss += __shfl_xor_sync(0xFFFFFFFFu, ss, o);
    float r = 1.0f / sqrtf(fmaxf(ss, 1e-12f));
    v.x *= r; v.y *= r; v.z *= r; v.w *= r;
    *(float4*)(p + lane * 4) = v;
    size_t o = (size_t)row * (2 * De) + lane * 4;
    bf16 h0 = __float2bfloat16(v.x), h1 = __float2bfloat16(v.y);
    bf16 h2 = __float2bfloat16(v.z), h3 = __float2bfloat16(v.w);
    __nv_bfloat162 p0; p0.x = h0; p0.y = h1;
    __nv_bfloat162 p1; p1.x = h2; p1.y = h3;
    *(__nv_bfloat162*)&m[o]     = p0;
    *(__nv_bfloat162*)&m[o + 2] = p1;
    __nv_bfloat162 q0, q1;
    q0.x = __float2bfloat16(v.x - __bfloat162float(h0));
    q0.y = __float2bfloat16(v.y - __bfloat162float(h1));
    q1.x = __float2bfloat16(v.z - __bfloat162float(h2));
    q1.y = __float2bfloat16(v.w - __bfloat162float(h3));
    *(__nv_bfloat162*)&m[o + De]     = q0;
    *(__nv_bfloat162*)&m[o + De + 2] = q1;
}

__global__ void lg_kernel(const float* __restrict__ qg, const float* __restrict__ kg,
                          float* __restrict__ out) {
    int row = blockIdx.x;
    __shared__ float qs[De];
    __shared__ float red[128];
    int t = threadIdx.x;
    qs[t] = qg[(size_t)row * De + t];
    __syncthreads();
    const float* kp = kg + (size_t)t * De;
    float dot = 0.f;
#pragma unroll 8
    for (int c = 0; c < De; c++) dot = fmaf(qs[c], kp[c], dot);
    float logit = dot * INV_TAU;          // |logit| <= 5: no max rescale needed
    red[t] = __expf(logit); __syncthreads();
    for (int s = 64; s; s >>= 1) { if (t < s) red[t] += red[t + s]; __syncthreads(); }
    float lse = logf(red[0]);
    if (t == row) out[row] = lse - logit;
}

__global__ void match_kernel(const float* __restrict__ qd, const float* __restrict__ kd,
                             bf16* __restrict__ mt, float* __restrict__ pos) {
    int row = blockIdx.x;
    int b = row / HW;
    __shared__ float qs[De];
    __shared__ float dots[64];
    __shared__ int   s_idx;
    __shared__ float s_val;
    int t = threadIdx.x;
    qs[t] = qd[(size_t)row * De + t];
    __syncthreads();
    if (t < HW) {
        const float* kp = kd + (size_t)(b * HW + t) * De;
        float d = 0.f;
#pragma unroll 8
        for (int c = 0; c < De; c++) d = fmaf(qs[c], kp[c], d);
        dots[t] = d;
    }
    __syncthreads();
    if (t == 0) {
        float bv = dots[0]; int bi = 0;
        for (int j = 1; j < HW; j++)
            if (dots[j] > bv) { bv = dots[j]; bi = j; }
        s_idx = bi; s_val = bv;
    }
    __syncthreads();
    float v = kd[(size_t)(b * HW + s_idx) * De + t];
    bf16 h = __float2bfloat16(v);
    size_t o = (size_t)row * (2 * De) + t;
    mt[o]      = h;
    mt[o + De] = __float2bfloat16(v - __bfloat162float(h));
    if (t == 0) pos[row] = s_val;
}

// final dense-LSE: sum 49 tile partials per row, log, minus positive
__global__ void lse_finish(const float* __restrict__ Spart, const float* __restrict__ pos,
                           float* __restrict__ out) {
    int row = blockIdx.x * 256 + threadIdx.x;
    if (row >= Nrow) return;
    float s = 0.f;
#pragma unroll
    for (int j = 0; j < NTILE; j++) s += Spart[(size_t)j * Nrow + row];
    out[row] = logf(s) - pos[row] * INV_TAU;
}

__global__ void final_kernel(const float* __restrict__ lg, const float* __restrict__ ld,
                             float* __restrict__ out) {
    int t = threadIdx.x;
    float s1 = 0.f, s2 = 0.f;
    if (t < Bn) s1 = lg[t];
    for (int j = t; j < Nrow; j += 256) s2 += ld[j];
    __shared__ float r1[256], r2[256];
    r1[t] = s1; r2[t] = s2; __syncthreads();
    for (int o = 128; o; o >>= 1) {
        if (t < o) { r1[t] += r1[t + o]; r2[t] += r2[t + o]; }
        __syncthreads();
    }
    if (t == 0) out[0] = 0.5f * (r1[0] / (float)Bn) + 0.5f * (r2[0] / (float)Nrow);
}

// ========================= host orchestration ================================
extern "C" void kernel_launch(void* const* d_in, const int* in_sizes, int n_in,
                              void* d_out, int out_size) {
    const float* feat_q = (const float*)d_in[0];
    const float* feat_k = (const float*)d_in[1];
    const float* Wg1  = (const float*)d_in[2];   const float* bg1 = (const float*)d_in[3];
    const float* Wg2  = (const float*)d_in[4];   const float* bg2 = (const float*)d_in[5];
    const float* Wd1  = (const float*)d_in[6];   const float* bd1 = (const float*)d_in[7];
    const float* Wd2  = (const float*)d_in[8];   const float* bd2 = (const float*)d_in[9];
    const float* mWg1 = (const float*)d_in[10];  const float* mbg1 = (const float*)d_in[11];
    const float* mWg2 = (const float*)d_in[12];  const float* mbg2 = (const float*)d_in[13];
    const float* mWd1 = (const float*)d_in[14];  const float* mbd1 = (const float*)d_in[15];
    const float* mWd2 = (const float*)d_in[16];  const float* mbd2 = (const float*)d_in[17];
    float* out = (float*)d_out;

    cudaFuncSetAttribute(gemm_mma<0>, cudaFuncAttributeMaxDynamicSharedMemorySize, SM_TOTAL);
    cudaFuncSetAttribute(gemm_mma<1>, cudaFuncAttributeMaxDynamicSharedMemorySize, SM_TOTAL);
    cudaFuncSetAttribute(gemm_mma<2>, cudaFuncAttributeMaxDynamicSharedMemorySize, SM_TOTAL);

#define SYM(p, s) cudaGetSymbolAddress((void**)&p, s)
    bf16 *Wd1T, *mWd1T, *Wg1T, *mWg1T, *Wg2T, *Wd2T, *mWg2T, *mWd2T;
    bf16 *Aq, *Ak, *pq, *pk, *gh, *hid, *qdm, *mt;
    float *part, *Spart, *qg, *kg, *qd, *kd, *pos, *lg, *ld;
    SYM(Wd1T, g_Wd1T); SYM(mWd1T, g_mWd1T); SYM(Wg1T, g_Wg1T); SYM(mWg1T, g_mWg1T);
    SYM(Wg2T, g_Wg2T); SYM(Wd2T, g_Wd2T); SYM(mWg2T, g_mWg2T); SYM(mWd2T, g_mWd2T);
    SYM(Aq, g_Aq); SYM(Ak, g_Ak); SYM(pq, g_pq); SYM(pk, g_pk);
    SYM(gh, g_gh); SYM(hid, g_hid); SYM(qdm, g_qdm); SYM(mt, g_mt);
    SYM(part, g_part); SYM(Spart, g_Spart);
    SYM(qg, g_qg); SYM(kg, g_kg); SYM(qd, g_qd); SYM(kd, g_kd);
    SYM(pos, g_pos); SYM(lg, g_lg); SYM(ld, g_ld);
#undef SYM

    // ---- pre-pass ----
    dim3 tb(32, 8);
    transpose_split<<<dim3(Dh/32, Cc/64), tb>>>(Wd1,  Wd1T,  Cc, Dh);
    transpose_split<<<dim3(Dh/32, Cc/64), tb>>>(mWd1, mWd1T, Cc, Dh);
    transpose_split<<<dim3(Dh/32, Cc/64), tb>>>(Wg1,  Wg1T,  Cc, Dh);
    transpose_split<<<dim3(Dh/32, Cc/64), tb>>>(mWg1, mWg1T, Cc, Dh);
    transpose_split<<<dim3(De/32, Dh/64), tb>>>(Wg2,  Wg2T,  Dh, De);
    transpose_split<<<dim3(De/32, Dh/64), tb>>>(Wd2,  Wd2T,  Dh, De);
    transpose_split<<<dim3(De/32, Dh/64), tb>>>(mWg2, mWg2T, Dh, De);
    transpose_split<<<dim3(De/32, Dh/64), tb>>>(mWd2, mWd2T, Dh, De);

    feat_prep<<<dim3(Cc/256, Bn), 256>>>(feat_q, Aq, pq);
    feat_prep<<<dim3(Cc/256, Bn), 256>>>(feat_k, Ak, pk);

    // ---- global head L1 (q+k merged, split-K 8) ----
    gemm_mma<0><<<dim3(Dh/128, 1, 16), 256, SM_TOTAL>>>(pq, pk, Wg1T, mWg1T,
        nullptr, nullptr, part, nullptr, Bn, Dh, 2*Cc, 2*Cc, Cc, Cc, 8, 0, 8);
    reduce_split<1><<<(Bn*Dh/4 + 255)/256, 256>>>(part, bg1, nullptr, gh, 8, (size_t)Bn*Dh, Dh);
    reduce_split<1><<<(Bn*Dh/4 + 255)/256, 256>>>(part + 8*(size_t)Bn*Dh, mbg1, nullptr,
        gh + (size_t)Bn*2*Dh, 8, (size_t)Bn*Dh, Dh);
    // ---- global head L2 (merged, split-K 16) ----
    gemm_mma<0><<<dim3(1, 1, 32), 256, SM_TOTAL>>>(gh, gh + (size_t)Bn*2*Dh, Wg2T, mWg2T,
        nullptr, nullptr, part, nullptr, Bn, De, 2*Dh, 2*Dh, Dh, Dh, 4, 0, 16);
    reduce_split<0><<<(Bn*De/4 + 255)/256, 256>>>(part, bg2, qg, nullptr, 16, (size_t)Bn*De, De);
    reduce_split<0><<<(Bn*De/4 + 255)/256, 256>>>(part + 16*(size_t)Bn*De, mbg2, kg, nullptr,
        16, (size_t)Bn*De, De);

    l2norm_kernel<<<(Bn + 7)/8, dim3(32, 8)>>>(qg, Bn);
    l2norm_kernel<<<(Bn + 7)/8, dim3(32, 8)>>>(kg, Bn);
    lg_kernel<<<Bn, 128>>>(qg, kg, lg);

    // ---- dense head L1 (q+k merged) ----
    gemm_mma<1><<<dim3(Dh/128, NTILE, 2), 256, SM_TOTAL>>>(Aq, Ak, Wd1T, mWd1T,
        bd1, mbd1, nullptr, hid, Nrow, Dh, 2*Cc, 2*Cc, Cc, Cc, 64, 0, 1);
    // ---- dense head L2 (merged, uneven split-K 3 -> 294 CTAs = 1 wave) ----
    gemm_mma<0><<<dim3(1, NTILE, 6), 256, SM_TOTAL>>>(hid, hid + (size_t)Nrow*2*Dh,
        Wd2T, mWd2T, nullptr, nullptr, part, nullptr, Nrow, De, 2*Dh, 2*Dh, Dh, Dh, 21, 1, 3);
    reduce_split<0><<<(Nrow*De/4 + 255)/256, 256>>>(part, bd2, qd, nullptr, 3, (size_t)Nrow*De, De);
    reduce_split<0><<<(Nrow*De/4 + 255)/256, 256>>>(part + 3*(size_t)Nrow*De, mbd2, kd, nullptr,
        3, (size_t)Nrow*De, De);

    l2norm_split<<<Nrow/8, dim3(32, 8)>>>(qd, qdm, Nrow);
    l2norm_kernel<<<Nrow/8, dim3(32, 8)>>>(kd, Nrow);

    // ---- matching + dense InfoNCE (fused exp epilogue) ----
    match_kernel<<<Nrow, 128>>>(qd, kd, mt, pos);
    gemm_mma<2><<<dim3(NTILE, NTILE, 1), 256, SM_TOTAL>>>(qdm, qdm, mt, mt,
        nullptr, nullptr, Spart, nullptr, Nrow, Nrow, 2*De, 2*De, De, De, 4, 0, 1);
    lse_finish<<<(Nrow + 255)/256, 256>>>(Spart, pos, ld);

    final_kernel<<<1, 256>>>(lg, ld, out);
}